// round 11
// baseline (speedup 1.0000x reference)
#include <cuda_runtime.h>
#include <cuda_fp16.h>
#include <cstdint>
#include <math.h>

// ---------------- problem constants ----------------
#define BB 2
#define SS 1024
#define HH 4096
#define NQ 32
#define NKV 8
#define DD 128
#define II 11008
#define TT (BB*SS)          // 2048 tokens
#define EPS 1e-5f

#define QKV_N (HH + 2*NKV*DD)   // 6144
#define GU_N  (2*II)            // 22016 (interleaved gate/up rows)

// ---------------- scratch (device globals, no allocation) ----------------
__device__ __half g_hin  [(size_t)TT*HH];
__device__ __half g_qkv  [(size_t)TT*QKV_N];
__device__ __half g_qh   [(size_t)TT*NQ*DD];
__device__ __half g_kh   [(size_t)TT*NKV*DD];
__device__ __half g_vt   [(size_t)TT*NKV*DD];
__device__ __half g_attn [(size_t)TT*HH];
__device__ float  g_h    [(size_t)TT*HH];
__device__ __half g_ffn  [(size_t)TT*II];
__device__ __half g_wqkv [(size_t)QKV_N*HH];
__device__ __half g_wo_t [(size_t)HH*HH];
__device__ __half g_wgu  [(size_t)GU_N*HH];
__device__ __half g_wd_t [(size_t)HH*II];

// ================= helpers =================
__device__ __forceinline__ uint32_t smem_u32(const void* p) {
    uint32_t a;
    asm("{ .reg .u64 t; cvta.to.shared.u64 t, %1; cvt.u32.u64 %0, t; }" : "=r"(a) : "l"(p));
    return a;
}
__device__ __forceinline__ void cp_async16(uint32_t dst, const void* src) {
    asm volatile("cp.async.cg.shared.global [%0], [%1], 16;" :: "r"(dst), "l"(src));
}
#define CP_COMMIT() asm volatile("cp.async.commit_group;" ::: "memory")
#define CP_WAIT(n)  asm volatile("cp.async.wait_group %0;" :: "n"(n) : "memory")

__device__ __forceinline__ void ldsm4(uint32_t addr, uint32_t& r0, uint32_t& r1,
                                      uint32_t& r2, uint32_t& r3) {
    asm volatile("ldmatrix.sync.aligned.m8n8.x4.shared.b16 {%0,%1,%2,%3}, [%4];"
                 : "=r"(r0), "=r"(r1), "=r"(r2), "=r"(r3) : "r"(addr));
}
__device__ __forceinline__ void mma_f16(float* d, const uint32_t* a, const uint32_t* b) {
    asm volatile(
        "mma.sync.aligned.m16n8k16.row.col.f32.f16.f16.f32 "
        "{%0,%1,%2,%3}, {%4,%5,%6,%7}, {%8,%9}, {%0,%1,%2,%3};\n"
        : "+f"(d[0]), "+f"(d[1]), "+f"(d[2]), "+f"(d[3])
        : "r"(a[0]), "r"(a[1]), "r"(a[2]), "r"(a[3]), "r"(b[0]), "r"(b[1]));
}
__device__ __forceinline__ uint32_t h2pack(float a, float b) {
    __half2 h = __floats2half2_rn(a, b);
    return *(uint32_t*)&h;
}

// ================= fp16 tensor-core GEMM =================
// C[M,N] = A[M,K] @ Bt[N,K]^T. CTA tile 128x256, BK=64, 3-stage cp.async,
// 512 threads = 16 warps (2m x 8n), warp tile 64x32, 1 CTA/SM (16 warps/SM).
// EPI 0: C = acc (fp32). EPI 1: C = res + acc (fp32).
// EPI 2: Chalf[M][N/2] = silu(acc_even) * acc_odd. EPI 3: Chalf = acc.
#define BM 128
#define BN 256
#define BK 64
#define GTHREADS 512
#define STAGES 3
#define ROWB 144                          // bytes per padded row (64 halves + 16B pad)
#define A_TILE (128*ROWB)                 // 18432
#define B_TILE (256*ROWB)                 // 36864
#define STAGE_B (A_TILE + B_TILE)         // 55296
#define SMEM_BYTES (STAGES*STAGE_B)       // 165888

__device__ __forceinline__ void load_stage(uint32_t sb, int st,
                                           const __half* __restrict__ A,
                                           const __half* __restrict__ B,
                                           int m0, int n0, int k0, int K) {
    int t = threadIdx.x;
    uint32_t sA = sb + st * STAGE_B;
    uint32_t sB = sA + A_TILE;
    #pragma unroll
    for (int i = 0; i < 2; i++) {                 // A: 128 rows x 8 chunks = 1024
        int c = t + i * GTHREADS;
        int row = c >> 3, ch = c & 7;
        cp_async16(sA + (uint32_t)(row * ROWB + ch * 16),
                   A + (size_t)(m0 + row) * K + k0 + ch * 8);
    }
    #pragma unroll
    for (int i = 0; i < 4; i++) {                 // B: 256 rows x 8 chunks = 2048
        int c = t + i * GTHREADS;
        int row = c >> 3, ch = c & 7;
        cp_async16(sB + (uint32_t)(row * ROWB + ch * 16),
                   B + (size_t)(n0 + row) * K + k0 + ch * 8);
    }
}

template<int EPI>
__global__ void __launch_bounds__(GTHREADS, 1)
hgemm(const __half* __restrict__ A, const __half* __restrict__ B,
      const float* __restrict__ res, void* __restrict__ Cout,
      int M, int N, int K) {
    extern __shared__ char smem[];
    uint32_t sb = smem_u32(smem);
    int tid = threadIdx.x, wid = tid >> 5, lane = tid & 31;
    int wm = wid >> 3, wn = wid & 7;               // 2 x 8 warps
    int group = lane >> 2, tig = lane & 3;
    int m0 = blockIdx.x * BM, n0 = blockIdx.y * BN;

    int rowoff = (lane & 7) + ((lane >> 3) & 1) * 8;
    int koff   = (lane >> 4) * 16;

    float acc[4][4][4];
    #pragma unroll
    for (int mt = 0; mt < 4; mt++)
        #pragma unroll
        for (int nt = 0; nt < 4; nt++)
            #pragma unroll
            for (int j = 0; j < 4; j++) acc[mt][nt][j] = 0.f;

    int nk = K / BK;
    // prologue: STAGES-1 = 2 stages in flight
    #pragma unroll
    for (int s = 0; s < STAGES - 1; s++) {
        load_stage(sb, s, A, B, m0, n0, s * BK, K);
        CP_COMMIT();
    }

    int st = 0;
    for (int kt = 0; kt < nk; kt++) {
        CP_WAIT(STAGES - 2);        // tile kt resident
        __syncthreads();            // all warps done reading the stage reused below

        int nxt = kt + STAGES - 1;
        if (nxt < nk) {
            int nst = st + (STAGES - 1); if (nst >= STAGES) nst -= STAGES;
            load_stage(sb, nst, A, B, m0, n0, nxt * BK, K);
        }
        CP_COMMIT();

        uint32_t sA = sb + st * STAGE_B;
        uint32_t sB = sA + A_TILE;

        #pragma unroll
        for (int ks = 0; ks < 4; ks++) {
            uint32_t a[4][4], bfr[4][2];
            #pragma unroll
            for (int mt = 0; mt < 4; mt++) {
                uint32_t ad = sA + (uint32_t)((wm * 64 + mt * 16 + rowoff) * ROWB + ks * 32 + koff);
                ldsm4(ad, a[mt][0], a[mt][1], a[mt][2], a[mt][3]);
            }
            #pragma unroll
            for (int np = 0; np < 2; np++) {
                uint32_t bd = sB + (uint32_t)((wn * 32 + np * 16 + rowoff) * ROWB + ks * 32 + koff);
                uint32_t r0, r1, r2, r3;
                ldsm4(bd, r0, r1, r2, r3);
                bfr[2*np][0] = r0; bfr[2*np][1] = r2;
                bfr[2*np+1][0] = r1; bfr[2*np+1][1] = r3;
            }
            #pragma unroll
            for (int mt = 0; mt < 4; mt++)
                #pragma unroll
                for (int nt = 0; nt < 4; nt++)
                    mma_f16(acc[mt][nt], a[mt], bfr[nt]);
        }
        if (++st == STAGES) st = 0;
    }

    // epilogue
    #pragma unroll
    for (int mt = 0; mt < 4; mt++) {
        int r0 = m0 + wm * 64 + mt * 16 + group;
        #pragma unroll
        for (int nt = 0; nt < 4; nt++) {
            int c = n0 + wn * 32 + nt * 8 + 2 * tig;     // always even
            if (EPI == 2) {
                __half* Ch = (__half*)Cout;
                int j = c >> 1;
                int No = N >> 1;
                float g0 = acc[mt][nt][0], u0 = acc[mt][nt][1];
                float g1 = acc[mt][nt][2], u1 = acc[mt][nt][3];
                Ch[(size_t)r0 * No + j]       = __float2half_rn(g0 / (1.f + __expf(-g0)) * u0);
                Ch[(size_t)(r0 + 8) * No + j] = __float2half_rn(g1 / (1.f + __expf(-g1)) * u1);
            } else if (EPI == 3) {
                __half* Ch = (__half*)Cout;
                size_t i0 = (size_t)r0 * N + c;
                size_t i1 = (size_t)(r0 + 8) * N + c;
                *(__half2*)(Ch + i0) = __floats2half2_rn(acc[mt][nt][0], acc[mt][nt][1]);
                *(__half2*)(Ch + i1) = __floats2half2_rn(acc[mt][nt][2], acc[mt][nt][3]);
            } else {
                float* C = (float*)Cout;
                size_t i0 = (size_t)r0 * N + c;
                size_t i1 = (size_t)(r0 + 8) * N + c;
                float2 v0 = make_float2(acc[mt][nt][0], acc[mt][nt][1]);
                float2 v1 = make_float2(acc[mt][nt][2], acc[mt][nt][3]);
                if (EPI == 1) {
                    float2 r0v = *(const float2*)(res + i0);
                    float2 r1v = *(const float2*)(res + i1);
                    v0.x += r0v.x; v0.y += r0v.y;
                    v1.x += r1v.x; v1.y += r1v.y;
                }
                *(float2*)(C + i0) = v0;
                *(float2*)(C + i1) = v1;
            }
        }
    }
}

// ================= weight pack (vectorized): W[K][N] fp32 -> Wt[n*str+off][K] =
__global__ void pack64(const float* __restrict__ W, __half* __restrict__ Wt,
                       int K, int N, int rowStride, int rowOff) {
    __shared__ float t[64][68];
    int k0 = blockIdx.x * 64, n0 = blockIdx.y * 64;
    int tid = threadIdx.x;
    int r = tid >> 4, c4 = (tid & 15) * 4;
    #pragma unroll
    for (int i = 0; i < 4; i++) {
        float4 v = *(const float4*)(W + (size_t)(k0 + r + i*16) * N + n0 + c4);
        *(float4*)&t[r + i*16][c4] = v;
    }
    __syncthreads();
    int n = tid >> 2, kq = (tid & 3) * 16;
    uint32_t h[8];
    #pragma unroll
    for (int j = 0; j < 8; j++) {
        __half2 hv = __floats2half2_rn(t[kq + 2*j][n], t[kq + 2*j + 1][n]);
        h[j] = *(uint32_t*)&hv;
    }
    __half* dst = Wt + ((size_t)(n0 + n) * rowStride + rowOff) * K + k0 + kq;
    *(uint4*)dst       = make_uint4(h[0], h[1], h[2], h[3]);
    *(uint4*)(dst + 8) = make_uint4(h[4], h[5], h[6], h[7]);
}

// ================= rmsnorm (half output) =================
__global__ void rmsnorm_kernel(const float* __restrict__ x,
                               const float* __restrict__ w,
                               __half* __restrict__ out) {
    int row = blockIdx.x;
    const float* xr = x + (size_t)row * HH;
    float ss = 0.f;
    for (int i = threadIdx.x; i < HH; i += blockDim.x) {
        float v = xr[i];
        ss = fmaf(v, v, ss);
    }
    __shared__ float red[32];
    int lane = threadIdx.x & 31, warp = threadIdx.x >> 5;
    #pragma unroll
    for (int off = 16; off; off >>= 1) ss += __shfl_xor_sync(~0u, ss, off);
    if (lane == 0) red[warp] = ss;
    __syncthreads();
    int nwarp = blockDim.x >> 5;
    if (warp == 0) {
        float v = (lane < nwarp) ? red[lane] : 0.f;
        #pragma unroll
        for (int off = 16; off; off >>= 1) v += __shfl_xor_sync(~0u, v, off);
        if (lane == 0) red[0] = v;
    }
    __syncthreads();
    float inv = rsqrtf(red[0] / (float)HH + EPS);
    __half* orow = out + (size_t)row * HH;
    for (int i = threadIdx.x; i < HH; i += blockDim.x)
        orow[i] = __float2half_rn(xr[i] * inv * w[i]);
}

// ================= RoPE extract: q (scaled) =================
__global__ void rope_q(const __half* __restrict__ qkv,
                       const float* __restrict__ cosT,
                       const float* __restrict__ sinT,
                       __half* __restrict__ qh) {
    int idx = blockIdx.x * blockDim.x + threadIdx.x;
    if (idx >= TT * NQ * 64) return;
    const float scale = 0.08838834764831845f;
    int d = idx & 63;
    int h = (idx >> 6) % NQ;
    int t = idx / (64 * NQ);
    int s = t % SS, b = t / SS;
    float c1 = cosT[s*DD + d],      s1 = sinT[s*DD + d];
    float c2 = cosT[s*DD + d + 64], s2 = sinT[s*DD + d + 64];
    const __half* p = qkv + (size_t)t * QKV_N + h * DD;
    float x1 = __half2float(p[d]), x2 = __half2float(p[d + 64]);
    size_t row = ((size_t)(b*NQ + h)*SS + s) * DD;
    qh[row + d]      = __float2half_rn((x1 * c1 - x2 * s1) * scale);
    qh[row + d + 64] = __float2half_rn((x2 * c2 + x1 * s2) * scale);
}

// ================= RoPE extract: k =================
__global__ void rope_k(const __half* __restrict__ qkv,
                       const float* __restrict__ cosT,
                       const float* __restrict__ sinT,
                       __half* __restrict__ kh) {
    int idx = blockIdx.x * blockDim.x + threadIdx.x;
    if (idx >= TT * NKV * 64) return;
    int d = idx & 63;
    int h = (idx >> 6) % NKV;
    int t = idx / (64 * NKV);
    int s = t % SS, b = t / SS;
    float c1 = cosT[s*DD + d],      s1 = sinT[s*DD + d];
    float c2 = cosT[s*DD + d + 64], s2 = sinT[s*DD + d + 64];
    const __half* p = qkv + (size_t)t * QKV_N + HH + h * DD;
    float x1 = __half2float(p[d]), x2 = __half2float(p[d + 64]);
    size_t row = ((size_t)(b*NKV + h)*SS + s) * DD;
    kh[row + d]      = __float2half_rn(x1 * c1 - x2 * s1);
    kh[row + d + 64] = __float2half_rn(x2 * c2 + x1 * s2);
}

// ================= V extract + transpose: vt[b,kvh,d,s] =================
__global__ void v_trans(const __half* __restrict__ qkv, __half* __restrict__ vt) {
    __shared__ __half tile[32][33];
    int s0 = blockIdx.x * 32, d0 = blockIdx.y * 32;
    int bk = blockIdx.z;
    int b = bk / NKV, kvh = bk % NKV;
    int tx = threadIdx.x, ty = threadIdx.y;
    #pragma unroll
    for (int i = 0; i < 32; i += 8) {
        int s = s0 + ty + i;
        tile[ty + i][tx] = qkv[(size_t)(b*SS + s) * QKV_N + HH + NKV*DD + kvh*DD + d0 + tx];
    }
    __syncthreads();
    #pragma unroll
    for (int i = 0; i < 32; i += 8)
        vt[((size_t)(b*NKV + kvh)*DD + d0 + ty + i) * SS + s0 + tx] = tile[tx][ty + i];
}

// ================= fp16 flash attention (unchanged) =================
#define AQT 64
#define AKT 64
#define QSTR 136
#define VSTR 72
#define AQ_BYTES (AQT*QSTR*2)
#define AK_BYTES (AKT*QSTR*2)
#define AV_BYTES (DD*VSTR*2)
#define ATT_SMEM (AQ_BYTES + 2*AK_BYTES + 2*AV_BYTES)

__global__ void __launch_bounds__(128, 2)
fattn(const __half* __restrict__ qh, const __half* __restrict__ kh,
      const __half* __restrict__ vt, __half* __restrict__ o) {
    extern __shared__ char sm[];
    uint32_t sb = smem_u32(sm);
    uint32_t sQ = sb;
    uint32_t sK = sQ + AQ_BYTES;
    uint32_t sV = sK + 2*AK_BYTES;

    int b = blockIdx.z, h = blockIdx.y;
    int qt = gridDim.x - 1 - blockIdx.x;
    int kvh = h >> 2;
    int q0 = qt * AQT;
    int tid = threadIdx.x, w = tid >> 5, lane = tid & 31;
    int g = lane >> 2, tig = lane & 3;
    int rowoff = lane & 15;
    int kofs   = (lane >> 4) * 16;

    const __half* qbase = qh + ((size_t)(b*NQ + h)*SS + q0) * DD;
    const __half* kbase = kh + ((size_t)(b*NKV + kvh)*SS) * DD;
    const __half* vbase = vt + ((size_t)(b*NKV + kvh)*DD) * SS;

    for (int i = tid; i < 1024; i += 128) {
        int r = i >> 4, c = i & 15;
        cp_async16(sQ + (uint32_t)(r*(QSTR*2) + c*16), qbase + (size_t)r*DD + c*8);
    }
    CP_COMMIT();

    int nt = qt + 1;
    {
        uint32_t dK = sK, dV = sV;
        for (int i = tid; i < 1024; i += 128) {
            int r = i >> 4, c = i & 15;
            cp_async16(dK + (uint32_t)(r*(QSTR*2) + c*16), kbase + (size_t)r*DD + c*8);
        }
        for (int i = tid; i < 1024; i += 128) {
            int r = i >> 3, c = i & 7;
            cp_async16(dV + (uint32_t)(r*(VSTR*2) + c*16), vbase + (size_t)r*SS + c*8);
        }
    }
    CP_COMMIT();

    CP_WAIT(1);
    __syncthreads();
    uint32_t qfr[8][4];
    #pragma unroll
    for (int kb = 0; kb < 8; kb++)
        ldsm4(sQ + (uint32_t)((w*16 + rowoff)*(QSTR*2) + kb*32 + kofs),
              qfr[kb][0], qfr[kb][1], qfr[kb][2], qfr[kb][3]);

    float m0v = -INFINITY, m1v = -INFINITY, l0 = 0.f, l1 = 0.f;
    float oac[16][4];
    #pragma unroll
    for (int i = 0; i < 16; i++)
        #pragma unroll
        for (int j = 0; j < 4; j++) oac[i][j] = 0.f;

    for (int t = 0; t < nt; t++) {
        if (t + 1 < nt) {
            uint32_t dK = sK + ((t+1)&1) * AK_BYTES;
            uint32_t dV = sV + ((t+1)&1) * AV_BYTES;
            const __half* kp = kbase + (size_t)(t+1)*AKT*DD;
            const __half* vp = vbase + (t+1)*AKT;
            for (int i = tid; i < 1024; i += 128) {
                int r = i >> 4, c = i & 15;
                cp_async16(dK + (uint32_t)(r*(QSTR*2) + c*16), kp + (size_t)r*DD + c*8);
            }
            for (int i = tid; i < 1024; i += 128) {
                int r = i >> 3, c = i & 7;
                cp_async16(dV + (uint32_t)(r*(VSTR*2) + c*16), vp + (size_t)r*SS + c*8);
            }
        }
        CP_COMMIT();
        CP_WAIT(1);
        __syncthreads();

        uint32_t cK = sK + (t&1) * AK_BYTES;
        uint32_t cV = sV + (t&1) * AV_BYTES;

        float s[8][4];
        #pragma unroll
        for (int j = 0; j < 8; j++)
            #pragma unroll
            for (int c = 0; c < 4; c++) s[j][c] = 0.f;

        #pragma unroll
        for (int kb = 0; kb < 8; kb++) {
            #pragma unroll
            for (int np = 0; np < 4; np++) {
                uint32_t r0, r1, r2, r3;
                ldsm4(cK + (uint32_t)((16*np + rowoff)*(QSTR*2) + kb*32 + kofs),
                      r0, r1, r2, r3);
                uint32_t b0[2] = {r0, r2}, b1[2] = {r1, r3};
                mma_f16(s[2*np],   qfr[kb], b0);
                mma_f16(s[2*np+1], qfr[kb], b1);
            }
        }

        if (t == qt) {
            int r0l = w*16 + g, r1l = r0l + 8;
            #pragma unroll
            for (int j = 0; j < 8; j++) {
                int c0 = 8*j + 2*tig;
                if (c0     > r0l) s[j][0] = -1e30f;
                if (c0 + 1 > r0l) s[j][1] = -1e30f;
                if (c0     > r1l) s[j][2] = -1e30f;
                if (c0 + 1 > r1l) s[j][3] = -1e30f;
            }
        }

        float tm0 = -1e30f, tm1 = -1e30f;
        #pragma unroll
        for (int j = 0; j < 8; j++) {
            tm0 = fmaxf(tm0, fmaxf(s[j][0], s[j][1]));
            tm1 = fmaxf(tm1, fmaxf(s[j][2], s[j][3]));
        }
        tm0 = fmaxf(tm0, __shfl_xor_sync(~0u, tm0, 1));
        tm0 = fmaxf(tm0, __shfl_xor_sync(~0u, tm0, 2));
        tm1 = fmaxf(tm1, __shfl_xor_sync(~0u, tm1, 1));
        tm1 = fmaxf(tm1, __shfl_xor_sync(~0u, tm1, 2));

        float mn0 = fmaxf(m0v, tm0), mn1 = fmaxf(m1v, tm1);
        float a0 = __expf(m0v - mn0), a1 = __expf(m1v - mn1);
        m0v = mn0; m1v = mn1;

        float ts0 = 0.f, ts1 = 0.f;
        #pragma unroll
        for (int j = 0; j < 8; j++) {
            s[j][0] = __expf(s[j][0] - mn0);
            s[j][1] = __expf(s[j][1] - mn0);
            s[j][2] = __expf(s[j][2] - mn1);
            s[j][3] = __expf(s[j][3] - mn1);
            ts0 += s[j][0] + s[j][1];
            ts1 += s[j][2] + s[j][3];
        }
        ts0 += __shfl_xor_sync(~0u, ts0, 1);
        ts0 += __shfl_xor_sync(~0u, ts0, 2);
        ts1 += __shfl_xor_sync(~0u, ts1, 1);
        ts1 += __shfl_xor_sync(~0u, ts1, 2);
        l0 = l0 * a0 + ts0;
        l1 = l1 * a1 + ts1;

        #pragma unroll
        for (int i = 0; i < 16; i++) {
            oac[i][0] *= a0; oac[i][1] *= a0;
            oac[i][2] *= a1; oac[i][3] *= a1;
        }

        uint32_t pf[4][4];
        #pragma unroll
        for (int jj = 0; jj < 4; jj++) {
            pf[jj][0] = h2pack(s[2*jj][0],   s[2*jj][1]);
            pf[jj][1] = h2pack(s[2*jj][2],   s[2*jj][3]);
            pf[jj][2] = h2pack(s[2*jj+1][0], s[2*jj+1][1]);
            pf[jj][3] = h2pack(s[2*jj+1][2], s[2*jj+1][3]);
        }

        #pragma unroll
        for (int jj = 0; jj < 4; jj++) {
            #pragma unroll
            for (int dp = 0; dp < 8; dp++) {
                uint32_t r0, r1, r2, r3;
                ldsm4(cV + (uint32_t)((16*dp + rowoff)*(VSTR*2) + jj*32 + kofs),
                      r0, r1, r2, r3);
                uint32_t b0[2] = {r0, r2}, b1[2] = {r1, r3};
                mma_f16(oac[2*dp],   pf[jj], b0);
                mma_f16(oac[2*dp+1], pf[jj], b1);
            }
        }
        __syncthreads();
    }

    float il0 = 1.f / l0, il1 = 1.f / l1;
    int r0g = q0 + w*16 + g;
    __half* ob0 = o + (size_t)(b*SS + r0g) * HH + h * DD;
    __half* ob1 = ob0 + (size_t)8 * HH;
    #pragma unroll
    for (int ntl = 0; ntl < 16; ntl++) {
        int d = 8*ntl + 2*tig;
        __half2 v0 = __floats2half2_rn(oac[ntl][0]*il0, oac[ntl][1]*il0);
        __half2 v1 = __floats2half2_rn(oac[ntl][2]*il1, oac[ntl][3]*il1);
        *(__half2*)(ob0 + d) = v0;
        *(__half2*)(ob1 + d) = v1;
    }
}

// ================= launch =================
extern "C" void kernel_launch(void* const* d_in, const int* in_sizes, int n_in,
                              void* d_out, int out_size) {
    const float* x     = (const float*)d_in[0];
    const float* cosT  = (const float*)d_in[1];
    const float* sinT  = (const float*)d_in[2];
    const float* anw   = (const float*)d_in[3];
    const float* fnw   = (const float*)d_in[4];
    const float* wq    = (const float*)d_in[5];
    const float* wk    = (const float*)d_in[6];
    const float* wv    = (const float*)d_in[7];
    const float* wo    = (const float*)d_in[8];
    const float* wgate = (const float*)d_in[9];
    const float* wup   = (const float*)d_in[10];
    const float* wdown = (const float*)d_in[11];
    float* out = (float*)d_out;

    __half *p_hin, *p_qkv, *p_qh, *p_kh, *p_vt, *p_attn, *p_ffn, *p_wqkv, *p_wo, *p_wgu, *p_wd;
    float *p_h;
    cudaGetSymbolAddress((void**)&p_hin,  g_hin);
    cudaGetSymbolAddress((void**)&p_qkv,  g_qkv);
    cudaGetSymbolAddress((void**)&p_qh,   g_qh);
    cudaGetSymbolAddress((void**)&p_kh,   g_kh);
    cudaGetSymbolAddress((void**)&p_vt,   g_vt);
    cudaGetSymbolAddress((void**)&p_attn, g_attn);
    cudaGetSymbolAddress((void**)&p_h,    g_h);
    cudaGetSymbolAddress((void**)&p_ffn,  g_ffn);
    cudaGetSymbolAddress((void**)&p_wqkv, g_wqkv);
    cudaGetSymbolAddress((void**)&p_wo,   g_wo_t);
    cudaGetSymbolAddress((void**)&p_wgu,  g_wgu);
    cudaGetSymbolAddress((void**)&p_wd,   g_wd_t);

    cudaFuncSetAttribute(hgemm<0>, cudaFuncAttributeMaxDynamicSharedMemorySize, SMEM_BYTES);
    cudaFuncSetAttribute(hgemm<1>, cudaFuncAttributeMaxDynamicSharedMemorySize, SMEM_BYTES);
    cudaFuncSetAttribute(hgemm<2>, cudaFuncAttributeMaxDynamicSharedMemorySize, SMEM_BYTES);
    cudaFuncSetAttribute(hgemm<3>, cudaFuncAttributeMaxDynamicSharedMemorySize, SMEM_BYTES);
    cudaFuncSetAttribute(fattn,    cudaFuncAttributeMaxDynamicSharedMemorySize, ATT_SMEM);

    // 0) attn rmsnorm -> half
    rmsnorm_kernel<<<TT, 256>>>(x, anw, p_hin);
    // 1-4) qkv + wo weight packs
    pack64<<<dim3(HH/64, HH/64), 256>>>(wq, p_wqkv, HH, HH, 1, 0);
    pack64<<<dim3(HH/64, (NKV*DD)/64), 256>>>(wk, p_wqkv + (size_t)HH*HH, HH, NKV*DD, 1, 0);
    pack64<<<dim3(HH/64, (NKV*DD)/64), 256>>>(wv, p_wqkv + (size_t)(HH+NKV*DD)*HH, HH, NKV*DD, 1, 0);
    pack64<<<dim3(HH/64, HH/64), 256>>>(wo, p_wo, HH, HH, 1, 0);
    // 5) fused qkv projection -> half
    hgemm<3><<<dim3(TT/BM, QKV_N/BN), GTHREADS, SMEM_BYTES>>>(p_hin, p_wqkv, nullptr, p_qkv, TT, QKV_N, HH);
    // 6-8) ffn weight packs (interleaved gate/up; down)
    pack64<<<dim3(HH/64, II/64), 256>>>(wgate, p_wgu, HH, II, 2, 0);
    pack64<<<dim3(HH/64, II/64), 256>>>(wup,   p_wgu, HH, II, 2, 1);
    pack64<<<dim3(II/64, HH/64), 256>>>(wdown, p_wd, II, HH, 1, 0);
    // 9-11) RoPE + extract into attention layouts
    {
        int tq = TT * NQ * 64;
        rope_q<<<(tq + 255) / 256, 256>>>(p_qkv, cosT, sinT, p_qh);
        int tk = TT * NKV * 64;
        rope_k<<<(tk + 255) / 256, 256>>>(p_qkv, cosT, sinT, p_kh);
        dim3 tb(32, 8);
        v_trans<<<dim3(SS/32, DD/32, BB*NKV), tb>>>(p_qkv, p_vt);
    }
    // 12) flash attention -> half [b,s,h,d]
    fattn<<<dim3(SS/AQT, NQ, BB), 128, ATT_SMEM>>>(p_qh, p_kh, p_vt, p_attn);
    // 13) output projection + residual: h = x + attn @ wo
    hgemm<1><<<dim3(TT/BM, HH/BN), GTHREADS, SMEM_BYTES>>>(p_attn, p_wo, x, p_h, TT, HH, HH);
    // 14) ffn rmsnorm -> half
    rmsnorm_kernel<<<TT, 256>>>(p_h, fnw, p_hin);
    // 15) fused gate+up with silu epilogue -> half [TT][II]
    hgemm<2><<<dim3(TT/BM, GU_N/BN), GTHREADS, SMEM_BYTES>>>(p_hin, p_wgu, nullptr, p_ffn, TT, GU_N, HH);
    // 16) down projection + residual: out = h + ffn @ wdown
    hgemm<1><<<dim3(TT/BM, HH/BN), GTHREADS, SMEM_BYTES>>>(p_ffn, p_wd, p_h, out, TT, HH, II);
}

// round 12
// speedup vs baseline: 1.0407x; 1.0407x over previous
#include <cuda_runtime.h>
#include <cuda_fp16.h>
#include <cstdint>
#include <math.h>

// ---------------- problem constants ----------------
#define BB 2
#define SS 1024
#define HH 4096
#define NQ 32
#define NKV 8
#define DD 128
#define II 11008
#define TT (BB*SS)          // 2048 tokens
#define EPS 1e-5f

#define QKV_N (HH + 2*NKV*DD)   // 6144
#define GU_N  (2*II)            // 22016 (interleaved gate/up rows)

// ---------------- scratch (device globals, no allocation) ----------------
__device__ __half g_hin  [(size_t)TT*HH];
__device__ __half g_qkv  [(size_t)TT*QKV_N];
__device__ __half g_qh   [(size_t)TT*NQ*DD];
__device__ __half g_kh   [(size_t)TT*NKV*DD];
__device__ __half g_vt   [(size_t)TT*NKV*DD];
__device__ __half g_attn [(size_t)TT*HH];
__device__ float  g_h    [(size_t)TT*HH];
__device__ __half g_ffn  [(size_t)TT*II];
__device__ __half g_wqkv [(size_t)QKV_N*HH];
__device__ __half g_wo_t [(size_t)HH*HH];
__device__ __half g_wgu  [(size_t)GU_N*HH];
__device__ __half g_wd_t [(size_t)HH*II];

// ================= helpers =================
__device__ __forceinline__ uint32_t smem_u32(const void* p) {
    uint32_t a;
    asm("{ .reg .u64 t; cvta.to.shared.u64 t, %1; cvt.u32.u64 %0, t; }" : "=r"(a) : "l"(p));
    return a;
}
__device__ __forceinline__ void cp_async16(uint32_t dst, const void* src) {
    asm volatile("cp.async.cg.shared.global [%0], [%1], 16;" :: "r"(dst), "l"(src));
}
#define CP_COMMIT() asm volatile("cp.async.commit_group;" ::: "memory")
#define CP_WAIT(n)  asm volatile("cp.async.wait_group %0;" :: "n"(n) : "memory")

__device__ __forceinline__ void ldsm4(uint32_t addr, uint32_t& r0, uint32_t& r1,
                                      uint32_t& r2, uint32_t& r3) {
    asm volatile("ldmatrix.sync.aligned.m8n8.x4.shared.b16 {%0,%1,%2,%3}, [%4];"
                 : "=r"(r0), "=r"(r1), "=r"(r2), "=r"(r3) : "r"(addr));
}
__device__ __forceinline__ void mma_f16(float* d, const uint32_t* a, const uint32_t* b) {
    asm volatile(
        "mma.sync.aligned.m16n8k16.row.col.f32.f16.f16.f32 "
        "{%0,%1,%2,%3}, {%4,%5,%6,%7}, {%8,%9}, {%0,%1,%2,%3};\n"
        : "+f"(d[0]), "+f"(d[1]), "+f"(d[2]), "+f"(d[3])
        : "r"(a[0]), "r"(a[1]), "r"(a[2]), "r"(a[3]), "r"(b[0]), "r"(b[1]));
}
__device__ __forceinline__ uint32_t h2pack(float a, float b) {
    __half2 h = __floats2half2_rn(a, b);
    return *(uint32_t*)&h;
}

// ================= fp16 tensor-core GEMM (R10-validated geometry) ============
// C[M,N] = A[M,K] @ Bt[N,K]^T. CTA tile 128x128, BK=64, 3-stage cp.async,
// 8 warps (2m x 4n), warp 64x32, 2 CTAs/SM. Single-sync mainloop.
// EPI 0: C = acc (fp32). EPI 1: C = res + acc (fp32).
// EPI 2: Chalf[M][N/2] = silu(acc_even) * acc_odd. EPI 3: Chalf = acc.
#define BM 128
#define BN 128
#define BK 64
#define STAGES 3
#define ROWB 144                          // bytes per padded row (64 halves + 16B pad)
#define TILE_BYTES (128*ROWB)             // 18432
#define STAGE_B (2*TILE_BYTES)            // 36864
#define SMEM_BYTES (STAGES*STAGE_B)       // 110592

__device__ __forceinline__ void load_stage(uint32_t sb, int st,
                                           const __half* __restrict__ A,
                                           const __half* __restrict__ B,
                                           int m0, int n0, int k0, int K) {
    int t = threadIdx.x;
    uint32_t sA = sb + st * STAGE_B;
    uint32_t sB = sA + TILE_BYTES;
    #pragma unroll
    for (int i = 0; i < 4; i++) {                 // A: 128 rows x 8 chunks
        int c = t + i * 256;
        int row = c >> 3, ch = c & 7;
        cp_async16(sA + (uint32_t)(row * ROWB + ch * 16),
                   A + (size_t)(m0 + row) * K + k0 + ch * 8);
    }
    #pragma unroll
    for (int i = 0; i < 4; i++) {                 // B: 128 rows x 8 chunks
        int c = t + i * 256;
        int row = c >> 3, ch = c & 7;
        cp_async16(sB + (uint32_t)(row * ROWB + ch * 16),
                   B + (size_t)(n0 + row) * K + k0 + ch * 8);
    }
}

template<int EPI>
__global__ void __launch_bounds__(256, 2)
hgemm(const __half* __restrict__ A, const __half* __restrict__ B,
      const float* __restrict__ res, void* __restrict__ Cout,
      int M, int N, int K) {
    extern __shared__ char smem[];
    uint32_t sb = smem_u32(smem);
    int tid = threadIdx.x, wid = tid >> 5, lane = tid & 31;
    int wm = wid >> 2, wn = wid & 3;
    int group = lane >> 2, tig = lane & 3;
    int m0 = blockIdx.x * BM, n0 = blockIdx.y * BN;

    int rowoff = (lane & 7) + ((lane >> 3) & 1) * 8;
    int koff   = (lane >> 4) * 16;

    float acc[4][4][4];
    #pragma unroll
    for (int mt = 0; mt < 4; mt++)
        #pragma unroll
        for (int nt = 0; nt < 4; nt++)
            #pragma unroll
            for (int j = 0; j < 4; j++) acc[mt][nt][j] = 0.f;

    int nk = K / BK;
    // prologue: STAGES-1 = 2 stages in flight
    #pragma unroll
    for (int s = 0; s < STAGES - 1; s++) {
        load_stage(sb, s, A, B, m0, n0, s * BK, K);
        CP_COMMIT();
    }

    int st = 0;
    for (int kt = 0; kt < nk; kt++) {
        CP_WAIT(STAGES - 2);        // tile kt resident
        __syncthreads();            // all warps done reading the stage reused below

        int nxt = kt + STAGES - 1;
        if (nxt < nk) {
            int nst = st + (STAGES - 1); if (nst >= STAGES) nst -= STAGES;
            load_stage(sb, nst, A, B, m0, n0, nxt * BK, K);
        }
        CP_COMMIT();

        uint32_t sA = sb + st * STAGE_B;
        uint32_t sB = sA + TILE_BYTES;

        #pragma unroll
        for (int ks = 0; ks < 4; ks++) {
            uint32_t a[4][4], bfr[4][2];
            #pragma unroll
            for (int mt = 0; mt < 4; mt++) {
                uint32_t ad = sA + (uint32_t)((wm * 64 + mt * 16 + rowoff) * ROWB + ks * 32 + koff);
                ldsm4(ad, a[mt][0], a[mt][1], a[mt][2], a[mt][3]);
            }
            #pragma unroll
            for (int np = 0; np < 2; np++) {
                uint32_t bd = sB + (uint32_t)((wn * 32 + np * 16 + rowoff) * ROWB + ks * 32 + koff);
                uint32_t r0, r1, r2, r3;
                ldsm4(bd, r0, r1, r2, r3);
                bfr[2*np][0] = r0; bfr[2*np][1] = r2;
                bfr[2*np+1][0] = r1; bfr[2*np+1][1] = r3;
            }
            #pragma unroll
            for (int mt = 0; mt < 4; mt++)
                #pragma unroll
                for (int nt = 0; nt < 4; nt++)
                    mma_f16(acc[mt][nt], a[mt], bfr[nt]);
        }
        if (++st == STAGES) st = 0;
    }

    // epilogue
    #pragma unroll
    for (int mt = 0; mt < 4; mt++) {
        int r0 = m0 + wm * 64 + mt * 16 + group;
        #pragma unroll
        for (int nt = 0; nt < 4; nt++) {
            int c = n0 + wn * 32 + nt * 8 + 2 * tig;     // always even
            if (EPI == 2) {
                __half* Ch = (__half*)Cout;
                int j = c >> 1;
                int No = N >> 1;
                float g0 = acc[mt][nt][0], u0 = acc[mt][nt][1];
                float g1 = acc[mt][nt][2], u1 = acc[mt][nt][3];
                Ch[(size_t)r0 * No + j]       = __float2half_rn(g0 / (1.f + __expf(-g0)) * u0);
                Ch[(size_t)(r0 + 8) * No + j] = __float2half_rn(g1 / (1.f + __expf(-g1)) * u1);
            } else if (EPI == 3) {
                __half* Ch = (__half*)Cout;
                size_t i0 = (size_t)r0 * N + c;
                size_t i1 = (size_t)(r0 + 8) * N + c;
                *(__half2*)(Ch + i0) = __floats2half2_rn(acc[mt][nt][0], acc[mt][nt][1]);
                *(__half2*)(Ch + i1) = __floats2half2_rn(acc[mt][nt][2], acc[mt][nt][3]);
            } else {
                float* C = (float*)Cout;
                size_t i0 = (size_t)r0 * N + c;
                size_t i1 = (size_t)(r0 + 8) * N + c;
                float2 v0 = make_float2(acc[mt][nt][0], acc[mt][nt][1]);
                float2 v1 = make_float2(acc[mt][nt][2], acc[mt][nt][3]);
                if (EPI == 1) {
                    float2 r0v = *(const float2*)(res + i0);
                    float2 r1v = *(const float2*)(res + i1);
                    v0.x += r0v.x; v0.y += r0v.y;
                    v1.x += r1v.x; v1.y += r1v.y;
                }
                *(float2*)(C + i0) = v0;
                *(float2*)(C + i1) = v1;
            }
        }
    }
}

// ================= weight pack (conflict-free): W[K][N] fp32 -> Wt[n*str+off][K]
// Read remap: warp reads 32 consecutive n at constant row -> bank-conflict-free
// LDS; each thread writes one full 32B gmem sector.
__global__ void pack64(const float* __restrict__ W, __half* __restrict__ Wt,
                       int K, int N, int rowStride, int rowOff) {
    __shared__ float t[64][68];
    int k0 = blockIdx.x * 64, n0 = blockIdx.y * 64;
    int tid = threadIdx.x;
    int r = tid >> 4, c4 = (tid & 15) * 4;
    #pragma unroll
    for (int i = 0; i < 4; i++) {
        float4 v = *(const float4*)(W + (size_t)(k0 + r + i*16) * N + n0 + c4);
        *(float4*)&t[r + i*16][c4] = v;
    }
    __syncthreads();
    int n = tid & 63, kq = (tid >> 6) * 16;     // warp: 32 consecutive n, fixed kq
    uint32_t h[8];
    #pragma unroll
    for (int j = 0; j < 8; j++) {
        __half2 hv = __floats2half2_rn(t[kq + 2*j][n], t[kq + 2*j + 1][n]);
        h[j] = *(uint32_t*)&hv;
    }
    __half* dst = Wt + ((size_t)(n0 + n) * rowStride + rowOff) * K + k0 + kq;
    *(uint4*)dst       = make_uint4(h[0], h[1], h[2], h[3]);
    *(uint4*)(dst + 8) = make_uint4(h[4], h[5], h[6], h[7]);
}

// ================= rmsnorm (half output) =================
__global__ void rmsnorm_kernel(const float* __restrict__ x,
                               const float* __restrict__ w,
                               __half* __restrict__ out) {
    int row = blockIdx.x;
    const float* xr = x + (size_t)row * HH;
    float ss = 0.f;
    for (int i = threadIdx.x; i < HH; i += blockDim.x) {
        float v = xr[i];
        ss = fmaf(v, v, ss);
    }
    __shared__ float red[32];
    int lane = threadIdx.x & 31, warp = threadIdx.x >> 5;
    #pragma unroll
    for (int off = 16; off; off >>= 1) ss += __shfl_xor_sync(~0u, ss, off);
    if (lane == 0) red[warp] = ss;
    __syncthreads();
    int nwarp = blockDim.x >> 5;
    if (warp == 0) {
        float v = (lane < nwarp) ? red[lane] : 0.f;
        #pragma unroll
        for (int off = 16; off; off >>= 1) v += __shfl_xor_sync(~0u, v, off);
        if (lane == 0) red[0] = v;
    }
    __syncthreads();
    float inv = rsqrtf(red[0] / (float)HH + EPS);
    __half* orow = out + (size_t)row * HH;
    for (int i = threadIdx.x; i < HH; i += blockDim.x)
        orow[i] = __float2half_rn(xr[i] * inv * w[i]);
}

// ================= RoPE extract: q (scaled) =================
__global__ void rope_q(const __half* __restrict__ qkv,
                       const float* __restrict__ cosT,
                       const float* __restrict__ sinT,
                       __half* __restrict__ qh) {
    int idx = blockIdx.x * blockDim.x + threadIdx.x;
    if (idx >= TT * NQ * 64) return;
    const float scale = 0.08838834764831845f;
    int d = idx & 63;
    int h = (idx >> 6) % NQ;
    int t = idx / (64 * NQ);
    int s = t % SS, b = t / SS;
    float c1 = cosT[s*DD + d],      s1 = sinT[s*DD + d];
    float c2 = cosT[s*DD + d + 64], s2 = sinT[s*DD + d + 64];
    const __half* p = qkv + (size_t)t * QKV_N + h * DD;
    float x1 = __half2float(p[d]), x2 = __half2float(p[d + 64]);
    size_t row = ((size_t)(b*NQ + h)*SS + s) * DD;
    qh[row + d]      = __float2half_rn((x1 * c1 - x2 * s1) * scale);
    qh[row + d + 64] = __float2half_rn((x2 * c2 + x1 * s2) * scale);
}

// ================= RoPE extract: k =================
__global__ void rope_k(const __half* __restrict__ qkv,
                       const float* __restrict__ cosT,
                       const float* __restrict__ sinT,
                       __half* __restrict__ kh) {
    int idx = blockIdx.x * blockDim.x + threadIdx.x;
    if (idx >= TT * NKV * 64) return;
    int d = idx & 63;
    int h = (idx >> 6) % NKV;
    int t = idx / (64 * NKV);
    int s = t % SS, b = t / SS;
    float c1 = cosT[s*DD + d],      s1 = sinT[s*DD + d];
    float c2 = cosT[s*DD + d + 64], s2 = sinT[s*DD + d + 64];
    const __half* p = qkv + (size_t)t * QKV_N + HH + h * DD;
    float x1 = __half2float(p[d]), x2 = __half2float(p[d + 64]);
    size_t row = ((size_t)(b*NKV + h)*SS + s) * DD;
    kh[row + d]      = __float2half_rn(x1 * c1 - x2 * s1);
    kh[row + d + 64] = __float2half_rn(x2 * c2 + x1 * s2);
}

// ================= V extract + transpose: vt[b,kvh,d,s] =================
__global__ void v_trans(const __half* __restrict__ qkv, __half* __restrict__ vt) {
    __shared__ __half tile[32][33];
    int s0 = blockIdx.x * 32, d0 = blockIdx.y * 32;
    int bk = blockIdx.z;
    int b = bk / NKV, kvh = bk % NKV;
    int tx = threadIdx.x, ty = threadIdx.y;
    #pragma unroll
    for (int i = 0; i < 32; i += 8) {
        int s = s0 + ty + i;
        tile[ty + i][tx] = qkv[(size_t)(b*SS + s) * QKV_N + HH + NKV*DD + kvh*DD + d0 + tx];
    }
    __syncthreads();
    #pragma unroll
    for (int i = 0; i < 32; i += 8)
        vt[((size_t)(b*NKV + kvh)*DD + d0 + ty + i) * SS + s0 + tx] = tile[tx][ty + i];
}

// ================= fp16 flash attention (unchanged) =================
#define AQT 64
#define AKT 64
#define QSTR 136
#define VSTR 72
#define AQ_BYTES (AQT*QSTR*2)
#define AK_BYTES (AKT*QSTR*2)
#define AV_BYTES (DD*VSTR*2)
#define ATT_SMEM (AQ_BYTES + 2*AK_BYTES + 2*AV_BYTES)

__global__ void __launch_bounds__(128, 2)
fattn(const __half* __restrict__ qh, const __half* __restrict__ kh,
      const __half* __restrict__ vt, __half* __restrict__ o) {
    extern __shared__ char sm[];
    uint32_t sb = smem_u32(sm);
    uint32_t sQ = sb;
    uint32_t sK = sQ + AQ_BYTES;
    uint32_t sV = sK + 2*AK_BYTES;

    int b = blockIdx.z, h = blockIdx.y;
    int qt = gridDim.x - 1 - blockIdx.x;
    int kvh = h >> 2;
    int q0 = qt * AQT;
    int tid = threadIdx.x, w = tid >> 5, lane = tid & 31;
    int g = lane >> 2, tig = lane & 3;
    int rowoff = lane & 15;
    int kofs   = (lane >> 4) * 16;

    const __half* qbase = qh + ((size_t)(b*NQ + h)*SS + q0) * DD;
    const __half* kbase = kh + ((size_t)(b*NKV + kvh)*SS) * DD;
    const __half* vbase = vt + ((size_t)(b*NKV + kvh)*DD) * SS;

    for (int i = tid; i < 1024; i += 128) {
        int r = i >> 4, c = i & 15;
        cp_async16(sQ + (uint32_t)(r*(QSTR*2) + c*16), qbase + (size_t)r*DD + c*8);
    }
    CP_COMMIT();

    int nt = qt + 1;
    {
        uint32_t dK = sK, dV = sV;
        for (int i = tid; i < 1024; i += 128) {
            int r = i >> 4, c = i & 15;
            cp_async16(dK + (uint32_t)(r*(QSTR*2) + c*16), kbase + (size_t)r*DD + c*8);
        }
        for (int i = tid; i < 1024; i += 128) {
            int r = i >> 3, c = i & 7;
            cp_async16(dV + (uint32_t)(r*(VSTR*2) + c*16), vbase + (size_t)r*SS + c*8);
        }
    }
    CP_COMMIT();

    CP_WAIT(1);
    __syncthreads();
    uint32_t qfr[8][4];
    #pragma unroll
    for (int kb = 0; kb < 8; kb++)
        ldsm4(sQ + (uint32_t)((w*16 + rowoff)*(QSTR*2) + kb*32 + kofs),
              qfr[kb][0], qfr[kb][1], qfr[kb][2], qfr[kb][3]);

    float m0v = -INFINITY, m1v = -INFINITY, l0 = 0.f, l1 = 0.f;
    float oac[16][4];
    #pragma unroll
    for (int i = 0; i < 16; i++)
        #pragma unroll
        for (int j = 0; j < 4; j++) oac[i][j] = 0.f;

    for (int t = 0; t < nt; t++) {
        if (t + 1 < nt) {
            uint32_t dK = sK + ((t+1)&1) * AK_BYTES;
            uint32_t dV = sV + ((t+1)&1) * AV_BYTES;
            const __half* kp = kbase + (size_t)(t+1)*AKT*DD;
            const __half* vp = vbase + (t+1)*AKT;
            for (int i = tid; i < 1024; i += 128) {
                int r = i >> 4, c = i & 15;
                cp_async16(dK + (uint32_t)(r*(QSTR*2) + c*16), kp + (size_t)r*DD + c*8);
            }
            for (int i = tid; i < 1024; i += 128) {
                int r = i >> 3, c = i & 7;
                cp_async16(dV + (uint32_t)(r*(VSTR*2) + c*16), vp + (size_t)r*SS + c*8);
            }
        }
        CP_COMMIT();
        CP_WAIT(1);
        __syncthreads();

        uint32_t cK = sK + (t&1) * AK_BYTES;
        uint32_t cV = sV + (t&1) * AV_BYTES;

        float s[8][4];
        #pragma unroll
        for (int j = 0; j < 8; j++)
            #pragma unroll
            for (int c = 0; c < 4; c++) s[j][c] = 0.f;

        #pragma unroll
        for (int kb = 0; kb < 8; kb++) {
            #pragma unroll
            for (int np = 0; np < 4; np++) {
                uint32_t r0, r1, r2, r3;
                ldsm4(cK + (uint32_t)((16*np + rowoff)*(QSTR*2) + kb*32 + kofs),
                      r0, r1, r2, r3);
                uint32_t b0[2] = {r0, r2}, b1[2] = {r1, r3};
                mma_f16(s[2*np],   qfr[kb], b0);
                mma_f16(s[2*np+1], qfr[kb], b1);
            }
        }

        if (t == qt) {
            int r0l = w*16 + g, r1l = r0l + 8;
            #pragma unroll
            for (int j = 0; j < 8; j++) {
                int c0 = 8*j + 2*tig;
                if (c0     > r0l) s[j][0] = -1e30f;
                if (c0 + 1 > r0l) s[j][1] = -1e30f;
                if (c0     > r1l) s[j][2] = -1e30f;
                if (c0 + 1 > r1l) s[j][3] = -1e30f;
            }
        }

        float tm0 = -1e30f, tm1 = -1e30f;
        #pragma unroll
        for (int j = 0; j < 8; j++) {
            tm0 = fmaxf(tm0, fmaxf(s[j][0], s[j][1]));
            tm1 = fmaxf(tm1, fmaxf(s[j][2], s[j][3]));
        }
        tm0 = fmaxf(tm0, __shfl_xor_sync(~0u, tm0, 1));
        tm0 = fmaxf(tm0, __shfl_xor_sync(~0u, tm0, 2));
        tm1 = fmaxf(tm1, __shfl_xor_sync(~0u, tm1, 1));
        tm1 = fmaxf(tm1, __shfl_xor_sync(~0u, tm1, 2));

        float mn0 = fmaxf(m0v, tm0), mn1 = fmaxf(m1v, tm1);
        float a0 = __expf(m0v - mn0), a1 = __expf(m1v - mn1);
        m0v = mn0; m1v = mn1;

        float ts0 = 0.f, ts1 = 0.f;
        #pragma unroll
        for (int j = 0; j < 8; j++) {
            s[j][0] = __expf(s[j][0] - mn0);
            s[j][1] = __expf(s[j][1] - mn0);
            s[j][2] = __expf(s[j][2] - mn1);
            s[j][3] = __expf(s[j][3] - mn1);
            ts0 += s[j][0] + s[j][1];
            ts1 += s[j][2] + s[j][3];
        }
        ts0 += __shfl_xor_sync(~0u, ts0, 1);
        ts0 += __shfl_xor_sync(~0u, ts0, 2);
        ts1 += __shfl_xor_sync(~0u, ts1, 1);
        ts1 += __shfl_xor_sync(~0u, ts1, 2);
        l0 = l0 * a0 + ts0;
        l1 = l1 * a1 + ts1;

        #pragma unroll
        for (int i = 0; i < 16; i++) {
            oac[i][0] *= a0; oac[i][1] *= a0;
            oac[i][2] *= a1; oac[i][3] *= a1;
        }

        uint32_t pf[4][4];
        #pragma unroll
        for (int jj = 0; jj < 4; jj++) {
            pf[jj][0] = h2pack(s[2*jj][0],   s[2*jj][1]);
            pf[jj][1] = h2pack(s[2*jj][2],   s[2*jj][3]);
            pf[jj][2] = h2pack(s[2*jj+1][0], s[2*jj+1][1]);
            pf[jj][3] = h2pack(s[2*jj+1][2], s[2*jj+1][3]);
        }

        #pragma unroll
        for (int jj = 0; jj < 4; jj++) {
            #pragma unroll
            for (int dp = 0; dp < 8; dp++) {
                uint32_t r0, r1, r2, r3;
                ldsm4(cV + (uint32_t)((16*dp + rowoff)*(VSTR*2) + jj*32 + kofs),
                      r0, r1, r2, r3);
                uint32_t b0[2] = {r0, r2}, b1[2] = {r1, r3};
                mma_f16(oac[2*dp],   pf[jj], b0);
                mma_f16(oac[2*dp+1], pf[jj], b1);
            }
        }
        __syncthreads();
    }

    float il0 = 1.f / l0, il1 = 1.f / l1;
    int r0g = q0 + w*16 + g;
    __half* ob0 = o + (size_t)(b*SS + r0g) * HH + h * DD;
    __half* ob1 = ob0 + (size_t)8 * HH;
    #pragma unroll
    for (int ntl = 0; ntl < 16; ntl++) {
        int d = 8*ntl + 2*tig;
        __half2 v0 = __floats2half2_rn(oac[ntl][0]*il0, oac[ntl][1]*il0);
        __half2 v1 = __floats2half2_rn(oac[ntl][2]*il1, oac[ntl][3]*il1);
        *(__half2*)(ob0 + d) = v0;
        *(__half2*)(ob1 + d) = v1;
    }
}

// ================= launch =================
extern "C" void kernel_launch(void* const* d_in, const int* in_sizes, int n_in,
                              void* d_out, int out_size) {
    const float* x     = (const float*)d_in[0];
    const float* cosT  = (const float*)d_in[1];
    const float* sinT  = (const float*)d_in[2];
    const float* anw   = (const float*)d_in[3];
    const float* fnw   = (const float*)d_in[4];
    const float* wq    = (const float*)d_in[5];
    const float* wk    = (const float*)d_in[6];
    const float* wv    = (const float*)d_in[7];
    const float* wo    = (const float*)d_in[8];
    const float* wgate = (const float*)d_in[9];
    const float* wup   = (const float*)d_in[10];
    const float* wdown = (const float*)d_in[11];
    float* out = (float*)d_out;

    __half *p_hin, *p_qkv, *p_qh, *p_kh, *p_vt, *p_attn, *p_ffn, *p_wqkv, *p_wo, *p_wgu, *p_wd;
    float *p_h;
    cudaGetSymbolAddress((void**)&p_hin,  g_hin);
    cudaGetSymbolAddress((void**)&p_qkv,  g_qkv);
    cudaGetSymbolAddress((void**)&p_qh,   g_qh);
    cudaGetSymbolAddress((void**)&p_kh,   g_kh);
    cudaGetSymbolAddress((void**)&p_vt,   g_vt);
    cudaGetSymbolAddress((void**)&p_attn, g_attn);
    cudaGetSymbolAddress((void**)&p_h,    g_h);
    cudaGetSymbolAddress((void**)&p_ffn,  g_ffn);
    cudaGetSymbolAddress((void**)&p_wqkv, g_wqkv);
    cudaGetSymbolAddress((void**)&p_wo,   g_wo_t);
    cudaGetSymbolAddress((void**)&p_wgu,  g_wgu);
    cudaGetSymbolAddress((void**)&p_wd,   g_wd_t);

    cudaFuncSetAttribute(hgemm<0>, cudaFuncAttributeMaxDynamicSharedMemorySize, SMEM_BYTES);
    cudaFuncSetAttribute(hgemm<1>, cudaFuncAttributeMaxDynamicSharedMemorySize, SMEM_BYTES);
    cudaFuncSetAttribute(hgemm<2>, cudaFuncAttributeMaxDynamicSharedMemorySize, SMEM_BYTES);
    cudaFuncSetAttribute(hgemm<3>, cudaFuncAttributeMaxDynamicSharedMemorySize, SMEM_BYTES);
    cudaFuncSetAttribute(fattn,    cudaFuncAttributeMaxDynamicSharedMemorySize, ATT_SMEM);

    // 0) attn rmsnorm -> half
    rmsnorm_kernel<<<TT, 256>>>(x, anw, p_hin);
    // 1-4) qkv + wo weight packs
    pack64<<<dim3(HH/64, HH/64), 256>>>(wq, p_wqkv, HH, HH, 1, 0);
    pack64<<<dim3(HH/64, (NKV*DD)/64), 256>>>(wk, p_wqkv + (size_t)HH*HH, HH, NKV*DD, 1, 0);
    pack64<<<dim3(HH/64, (NKV*DD)/64), 256>>>(wv, p_wqkv + (size_t)(HH+NKV*DD)*HH, HH, NKV*DD, 1, 0);
    pack64<<<dim3(HH/64, HH/64), 256>>>(wo, p_wo, HH, HH, 1, 0);
    // 5) fused qkv projection -> half
    hgemm<3><<<dim3(TT/BM, QKV_N/BN), 256, SMEM_BYTES>>>(p_hin, p_wqkv, nullptr, p_qkv, TT, QKV_N, HH);
    // 6-8) ffn weight packs (interleaved gate/up; down)
    pack64<<<dim3(HH/64, II/64), 256>>>(wgate, p_wgu, HH, II, 2, 0);
    pack64<<<dim3(HH/64, II/64), 256>>>(wup,   p_wgu, HH, II, 2, 1);
    pack64<<<dim3(II/64, HH/64), 256>>>(wdown, p_wd, II, HH, 1, 0);
    // 9-11) RoPE + extract into attention layouts
    {
        int tq = TT * NQ * 64;
        rope_q<<<(tq + 255) / 256, 256>>>(p_qkv, cosT, sinT, p_qh);
        int tk = TT * NKV * 64;
        rope_k<<<(tk + 255) / 256, 256>>>(p_qkv, cosT, sinT, p_kh);
        dim3 tb(32, 8);
        v_trans<<<dim3(SS/32, DD/32, BB*NKV), tb>>>(p_qkv, p_vt);
    }
    // 12) flash attention -> half [b,s,h,d]
    fattn<<<dim3(SS/AQT, NQ, BB), 128, ATT_SMEM>>>(p_qh, p_kh, p_vt, p_attn);
    // 13) output projection + residual: h = x + attn @ wo
    hgemm<1><<<dim3(TT/BM, HH/BN), 256, SMEM_BYTES>>>(p_attn, p_wo, x, p_h, TT, HH, HH);
    // 14) ffn rmsnorm -> half
    rmsnorm_kernel<<<TT, 256>>>(p_h, fnw, p_hin);
    // 15) fused gate+up with silu epilogue -> half [TT][II]
    hgemm<2><<<dim3(TT/BM, GU_N/BN), 256, SMEM_BYTES>>>(p_hin, p_wgu, nullptr, p_ffn, TT, GU_N, HH);
    // 16) down projection + residual: out = h + ffn @ wdown
    hgemm<1><<<dim3(TT/BM, HH/BN), 256, SMEM_BYTES>>>(p_ffn, p_wd, p_h, out, TT, HH, II);
}

// round 13
// speedup vs baseline: 1.0551x; 1.0138x over previous
#include <cuda_runtime.h>
#include <cuda_fp16.h>
#include <cstdint>
#include <math.h>

// ---------------- problem constants ----------------
#define BB 2
#define SS 1024
#define HH 4096
#define NQ 32
#define NKV 8
#define DD 128
#define II 11008
#define TT (BB*SS)          // 2048 tokens
#define EPS 1e-5f

#define QKV_N (HH + 2*NKV*DD)   // 6144
#define GU_N  (2*II)            // 22016 (interleaved gate/up rows)

// ---------------- scratch (device globals, no allocation) ----------------
__device__ __half g_hin  [(size_t)TT*HH];
__device__ __half g_qkv  [(size_t)TT*QKV_N];
__device__ __half g_qh   [(size_t)TT*NQ*DD];
__device__ __half g_kh   [(size_t)TT*NKV*DD];
__device__ __half g_vt   [(size_t)TT*NKV*DD];
__device__ __half g_attn [(size_t)TT*HH];
__device__ float  g_h    [(size_t)TT*HH];
__device__ __half g_ffn  [(size_t)TT*II];
__device__ __half g_wqkv [(size_t)QKV_N*HH];
__device__ __half g_wo_t [(size_t)HH*HH];
__device__ __half g_wgu  [(size_t)GU_N*HH];
__device__ __half g_wd_t [(size_t)HH*II];

// ================= helpers =================
__device__ __forceinline__ uint32_t smem_u32(const void* p) {
    uint32_t a;
    asm("{ .reg .u64 t; cvta.to.shared.u64 t, %1; cvt.u32.u64 %0, t; }" : "=r"(a) : "l"(p));
    return a;
}
__device__ __forceinline__ void cp_async16(uint32_t dst, const void* src) {
    asm volatile("cp.async.cg.shared.global [%0], [%1], 16;" :: "r"(dst), "l"(src));
}
#define CP_COMMIT() asm volatile("cp.async.commit_group;" ::: "memory")
#define CP_WAIT(n)  asm volatile("cp.async.wait_group %0;" :: "n"(n) : "memory")

__device__ __forceinline__ void ldsm4(uint32_t addr, uint32_t& r0, uint32_t& r1,
                                      uint32_t& r2, uint32_t& r3) {
    asm volatile("ldmatrix.sync.aligned.m8n8.x4.shared.b16 {%0,%1,%2,%3}, [%4];"
                 : "=r"(r0), "=r"(r1), "=r"(r2), "=r"(r3) : "r"(addr));
}
__device__ __forceinline__ void mma_f16(float* d, const uint32_t* a, const uint32_t* b) {
    asm volatile(
        "mma.sync.aligned.m16n8k16.row.col.f32.f16.f16.f32 "
        "{%0,%1,%2,%3}, {%4,%5,%6,%7}, {%8,%9}, {%0,%1,%2,%3};\n"
        : "+f"(d[0]), "+f"(d[1]), "+f"(d[2]), "+f"(d[3])
        : "r"(a[0]), "r"(a[1]), "r"(a[2]), "r"(a[3]), "r"(b[0]), "r"(b[1]));
}
__device__ __forceinline__ uint32_t h2pack(float a, float b) {
    __half2 h = __floats2half2_rn(a, b);
    return *(uint32_t*)&h;
}

// ================= fp16 tensor-core GEMM (R10-validated geometry) ============
// C[M,N] = A[M,K] @ Bt[N,K]^T. CTA tile 128x128, BK=64, 3-stage cp.async,
// 8 warps (2m x 4n), warp 64x32, 2 CTAs/SM. Single-sync mainloop.
// EPI 0: C = acc (fp32). EPI 1: C = res + acc (fp32).
// EPI 2: Chalf[M][N/2] = silu(acc_even) * acc_odd. EPI 3: Chalf = acc.
#define BM 128
#define BN 128
#define BK 64
#define STAGES 3
#define ROWB 144                          // bytes per padded row (64 halves + 16B pad)
#define TILE_BYTES (128*ROWB)             // 18432
#define STAGE_B (2*TILE_BYTES)            // 36864
#define SMEM_BYTES (STAGES*STAGE_B)       // 110592

__device__ __forceinline__ void load_stage(uint32_t sb, int st,
                                           const __half* __restrict__ A,
                                           const __half* __restrict__ B,
                                           int m0, int n0, int k0, int K) {
    int t = threadIdx.x;
    uint32_t sA = sb + st * STAGE_B;
    uint32_t sB = sA + TILE_BYTES;
    #pragma unroll
    for (int i = 0; i < 4; i++) {                 // A: 128 rows x 8 chunks
        int c = t + i * 256;
        int row = c >> 3, ch = c & 7;
        cp_async16(sA + (uint32_t)(row * ROWB + ch * 16),
                   A + (size_t)(m0 + row) * K + k0 + ch * 8);
    }
    #pragma unroll
    for (int i = 0; i < 4; i++) {                 // B: 128 rows x 8 chunks
        int c = t + i * 256;
        int row = c >> 3, ch = c & 7;
        cp_async16(sB + (uint32_t)(row * ROWB + ch * 16),
                   B + (size_t)(n0 + row) * K + k0 + ch * 8);
    }
}

template<int EPI>
__global__ void __launch_bounds__(256, 2)
hgemm(const __half* __restrict__ A, const __half* __restrict__ B,
      const float* __restrict__ res, void* __restrict__ Cout,
      int M, int N, int K) {
    extern __shared__ char smem[];
    uint32_t sb = smem_u32(smem);
    int tid = threadIdx.x, wid = tid >> 5, lane = tid & 31;
    int wm = wid >> 2, wn = wid & 3;
    int group = lane >> 2, tig = lane & 3;
    int m0 = blockIdx.x * BM, n0 = blockIdx.y * BN;

    int rowoff = (lane & 7) + ((lane >> 3) & 1) * 8;
    int koff   = (lane >> 4) * 16;

    float acc[4][4][4];
    #pragma unroll
    for (int mt = 0; mt < 4; mt++)
        #pragma unroll
        for (int nt = 0; nt < 4; nt++)
            #pragma unroll
            for (int j = 0; j < 4; j++) acc[mt][nt][j] = 0.f;

    int nk = K / BK;
    // prologue: STAGES-1 = 2 stages in flight
    #pragma unroll
    for (int s = 0; s < STAGES - 1; s++) {
        load_stage(sb, s, A, B, m0, n0, s * BK, K);
        CP_COMMIT();
    }

    int st = 0;
    for (int kt = 0; kt < nk; kt++) {
        CP_WAIT(STAGES - 2);        // tile kt resident
        __syncthreads();            // all warps done reading the stage reused below

        int nxt = kt + STAGES - 1;
        if (nxt < nk) {
            int nst = st + (STAGES - 1); if (nst >= STAGES) nst -= STAGES;
            load_stage(sb, nst, A, B, m0, n0, nxt * BK, K);
        }
        CP_COMMIT();

        uint32_t sA = sb + st * STAGE_B;
        uint32_t sB = sA + TILE_BYTES;

        #pragma unroll
        for (int ks = 0; ks < 4; ks++) {
            uint32_t a[4][4], bfr[4][2];
            #pragma unroll
            for (int mt = 0; mt < 4; mt++) {
                uint32_t ad = sA + (uint32_t)((wm * 64 + mt * 16 + rowoff) * ROWB + ks * 32 + koff);
                ldsm4(ad, a[mt][0], a[mt][1], a[mt][2], a[mt][3]);
            }
            #pragma unroll
            for (int np = 0; np < 2; np++) {
                uint32_t bd = sB + (uint32_t)((wn * 32 + np * 16 + rowoff) * ROWB + ks * 32 + koff);
                uint32_t r0, r1, r2, r3;
                ldsm4(bd, r0, r1, r2, r3);
                bfr[2*np][0] = r0; bfr[2*np][1] = r2;
                bfr[2*np+1][0] = r1; bfr[2*np+1][1] = r3;
            }
            #pragma unroll
            for (int mt = 0; mt < 4; mt++)
                #pragma unroll
                for (int nt = 0; nt < 4; nt++)
                    mma_f16(acc[mt][nt], a[mt], bfr[nt]);
        }
        if (++st == STAGES) st = 0;
    }

    // epilogue
    #pragma unroll
    for (int mt = 0; mt < 4; mt++) {
        int r0 = m0 + wm * 64 + mt * 16 + group;
        #pragma unroll
        for (int nt = 0; nt < 4; nt++) {
            int c = n0 + wn * 32 + nt * 8 + 2 * tig;     // always even
            if (EPI == 2) {
                __half* Ch = (__half*)Cout;
                int j = c >> 1;
                int No = N >> 1;
                float g0 = acc[mt][nt][0], u0 = acc[mt][nt][1];
                float g1 = acc[mt][nt][2], u1 = acc[mt][nt][3];
                Ch[(size_t)r0 * No + j]       = __float2half_rn(g0 / (1.f + __expf(-g0)) * u0);
                Ch[(size_t)(r0 + 8) * No + j] = __float2half_rn(g1 / (1.f + __expf(-g1)) * u1);
            } else if (EPI == 3) {
                __half* Ch = (__half*)Cout;
                size_t i0 = (size_t)r0 * N + c;
                size_t i1 = (size_t)(r0 + 8) * N + c;
                *(__half2*)(Ch + i0) = __floats2half2_rn(acc[mt][nt][0], acc[mt][nt][1]);
                *(__half2*)(Ch + i1) = __floats2half2_rn(acc[mt][nt][2], acc[mt][nt][3]);
            } else {
                float* C = (float*)Cout;
                size_t i0 = (size_t)r0 * N + c;
                size_t i1 = (size_t)(r0 + 8) * N + c;
                float2 v0 = make_float2(acc[mt][nt][0], acc[mt][nt][1]);
                float2 v1 = make_float2(acc[mt][nt][2], acc[mt][nt][3]);
                if (EPI == 1) {
                    float2 r0v = *(const float2*)(res + i0);
                    float2 r1v = *(const float2*)(res + i1);
                    v0.x += r0v.x; v0.y += r0v.y;
                    v1.x += r1v.x; v1.y += r1v.y;
                }
                *(float2*)(C + i0) = v0;
                *(float2*)(C + i1) = v1;
            }
        }
    }
}

// ================= weight pack: W[K][N] fp32 -> Wt[n*str+off][K] half =========
// smem XOR-8 swizzle (keyed on (row>>4)&3) -> conflict-free LDS reads;
// quad-per-row output mapping -> contiguous 128B gmem write segments.
__global__ void pack64(const float* __restrict__ W, __half* __restrict__ Wt,
                       int K, int N, int rowStride, int rowOff) {
    __shared__ float t[64 * 68];
    int k0 = blockIdx.x * 64, n0 = blockIdx.y * 64;
    int tid = threadIdx.x;
    int r = tid >> 4, c4 = (tid & 15) * 4;
    #pragma unroll
    for (int i = 0; i < 4; i++) {
        int rr = r + i * 16;
        float4 v = *(const float4*)(W + (size_t)(k0 + rr) * N + n0 + c4);
        int sc = c4 ^ (((rr >> 4) & 3) * 8);
        *(float4*)&t[rr * 68 + sc] = v;
    }
    __syncthreads();
    int n = tid >> 2, kq = (tid & 3) * 16;      // quad covers one n-row, 128B out
    uint32_t h[8];
    #pragma unroll
    for (int j = 0; j < 8; j++) {
        int r1 = kq + 2 * j;                    // r1>>4 == (tid&3) for all j
        int sw = ((r1 >> 4) & 3) * 8;
        float a = t[r1 * 68 + (n ^ sw)];
        float b = t[(r1 + 1) * 68 + (n ^ sw)];
        __half2 hv = __floats2half2_rn(a, b);
        h[j] = *(uint32_t*)&hv;
    }
    __half* dst = Wt + ((size_t)(n0 + n) * rowStride + rowOff) * K + k0 + kq;
    *(uint4*)dst       = make_uint4(h[0], h[1], h[2], h[3]);
    *(uint4*)(dst + 8) = make_uint4(h[4], h[5], h[6], h[7]);
}

// ================= rmsnorm (half output) =================
__global__ void rmsnorm_kernel(const float* __restrict__ x,
                               const float* __restrict__ w,
                               __half* __restrict__ out) {
    int row = blockIdx.x;
    const float* xr = x + (size_t)row * HH;
    float ss = 0.f;
    for (int i = threadIdx.x; i < HH; i += blockDim.x) {
        float v = xr[i];
        ss = fmaf(v, v, ss);
    }
    __shared__ float red[32];
    int lane = threadIdx.x & 31, warp = threadIdx.x >> 5;
    #pragma unroll
    for (int off = 16; off; off >>= 1) ss += __shfl_xor_sync(~0u, ss, off);
    if (lane == 0) red[warp] = ss;
    __syncthreads();
    int nwarp = blockDim.x >> 5;
    if (warp == 0) {
        float v = (lane < nwarp) ? red[lane] : 0.f;
        #pragma unroll
        for (int off = 16; off; off >>= 1) v += __shfl_xor_sync(~0u, v, off);
        if (lane == 0) red[0] = v;
    }
    __syncthreads();
    float inv = rsqrtf(red[0] / (float)HH + EPS);
    __half* orow = out + (size_t)row * HH;
    for (int i = threadIdx.x; i < HH; i += blockDim.x)
        orow[i] = __float2half_rn(xr[i] * inv * w[i]);
}

// ================= fused RoPE extract: q (scaled) + k =================
__global__ void rope_qk(const __half* __restrict__ qkv,
                        const float* __restrict__ cosT,
                        const float* __restrict__ sinT,
                        __half* __restrict__ qh,
                        __half* __restrict__ kh) {
    int idx = blockIdx.x * blockDim.x + threadIdx.x;
    if (idx >= TT * (NQ + NKV) * 64) return;
    const float qscale = 0.08838834764831845f;
    int d  = idx & 63;
    int hh = (idx >> 6) % (NQ + NKV);
    int t  = idx / (64 * (NQ + NKV));
    int s  = t % SS, b = t / SS;
    float c1 = cosT[s*DD + d],      s1 = sinT[s*DD + d];
    float c2 = cosT[s*DD + d + 64], s2 = sinT[s*DD + d + 64];
    if (hh < NQ) {
        const __half* p = qkv + (size_t)t * QKV_N + hh * DD;
        float x1 = __half2float(p[d]), x2 = __half2float(p[d + 64]);
        size_t row = ((size_t)(b*NQ + hh)*SS + s) * DD;
        qh[row + d]      = __float2half_rn((x1 * c1 - x2 * s1) * qscale);
        qh[row + d + 64] = __float2half_rn((x2 * c2 + x1 * s2) * qscale);
    } else {
        int h = hh - NQ;
        const __half* p = qkv + (size_t)t * QKV_N + HH + h * DD;
        float x1 = __half2float(p[d]), x2 = __half2float(p[d + 64]);
        size_t row = ((size_t)(b*NKV + h)*SS + s) * DD;
        kh[row + d]      = __float2half_rn(x1 * c1 - x2 * s1);
        kh[row + d + 64] = __float2half_rn(x2 * c2 + x1 * s2);
    }
}

// ================= V extract + transpose: vt[b,kvh,d,s] =================
__global__ void v_trans(const __half* __restrict__ qkv, __half* __restrict__ vt) {
    __shared__ __half tile[32][33];
    int s0 = blockIdx.x * 32, d0 = blockIdx.y * 32;
    int bk = blockIdx.z;
    int b = bk / NKV, kvh = bk % NKV;
    int tx = threadIdx.x, ty = threadIdx.y;
    #pragma unroll
    for (int i = 0; i < 32; i += 8) {
        int s = s0 + ty + i;
        tile[ty + i][tx] = qkv[(size_t)(b*SS + s) * QKV_N + HH + NKV*DD + kvh*DD + d0 + tx];
    }
    __syncthreads();
    #pragma unroll
    for (int i = 0; i < 32; i += 8)
        vt[((size_t)(b*NKV + kvh)*DD + d0 + ty + i) * SS + s0 + tx] = tile[tx][ty + i];
}

// ================= fp16 flash attention (unchanged) =================
#define AQT 64
#define AKT 64
#define QSTR 136
#define VSTR 72
#define AQ_BYTES (AQT*QSTR*2)
#define AK_BYTES (AKT*QSTR*2)
#define AV_BYTES (DD*VSTR*2)
#define ATT_SMEM (AQ_BYTES + 2*AK_BYTES + 2*AV_BYTES)

__global__ void __launch_bounds__(128, 2)
fattn(const __half* __restrict__ qh, const __half* __restrict__ kh,
      const __half* __restrict__ vt, __half* __restrict__ o) {
    extern __shared__ char sm[];
    uint32_t sb = smem_u32(sm);
    uint32_t sQ = sb;
    uint32_t sK = sQ + AQ_BYTES;
    uint32_t sV = sK + 2*AK_BYTES;

    int b = blockIdx.z, h = blockIdx.y;
    int qt = gridDim.x - 1 - blockIdx.x;
    int kvh = h >> 2;
    int q0 = qt * AQT;
    int tid = threadIdx.x, w = tid >> 5, lane = tid & 31;
    int g = lane >> 2, tig = lane & 3;
    int rowoff = lane & 15;
    int kofs   = (lane >> 4) * 16;

    const __half* qbase = qh + ((size_t)(b*NQ + h)*SS + q0) * DD;
    const __half* kbase = kh + ((size_t)(b*NKV + kvh)*SS) * DD;
    const __half* vbase = vt + ((size_t)(b*NKV + kvh)*DD) * SS;

    for (int i = tid; i < 1024; i += 128) {
        int r = i >> 4, c = i & 15;
        cp_async16(sQ + (uint32_t)(r*(QSTR*2) + c*16), qbase + (size_t)r*DD + c*8);
    }
    CP_COMMIT();

    int nt = qt + 1;
    {
        uint32_t dK = sK, dV = sV;
        for (int i = tid; i < 1024; i += 128) {
            int r = i >> 4, c = i & 15;
            cp_async16(dK + (uint32_t)(r*(QSTR*2) + c*16), kbase + (size_t)r*DD + c*8);
        }
        for (int i = tid; i < 1024; i += 128) {
            int r = i >> 3, c = i & 7;
            cp_async16(dV + (uint32_t)(r*(VSTR*2) + c*16), vbase + (size_t)r*SS + c*8);
        }
    }
    CP_COMMIT();

    CP_WAIT(1);
    __syncthreads();
    uint32_t qfr[8][4];
    #pragma unroll
    for (int kb = 0; kb < 8; kb++)
        ldsm4(sQ + (uint32_t)((w*16 + rowoff)*(QSTR*2) + kb*32 + kofs),
              qfr[kb][0], qfr[kb][1], qfr[kb][2], qfr[kb][3]);

    float m0v = -INFINITY, m1v = -INFINITY, l0 = 0.f, l1 = 0.f;
    float oac[16][4];
    #pragma unroll
    for (int i = 0; i < 16; i++)
        #pragma unroll
        for (int j = 0; j < 4; j++) oac[i][j] = 0.f;

    for (int t = 0; t < nt; t++) {
        if (t + 1 < nt) {
            uint32_t dK = sK + ((t+1)&1) * AK_BYTES;
            uint32_t dV = sV + ((t+1)&1) * AV_BYTES;
            const __half* kp = kbase + (size_t)(t+1)*AKT*DD;
            const __half* vp = vbase + (t+1)*AKT;
            for (int i = tid; i < 1024; i += 128) {
                int r = i >> 4, c = i & 15;
                cp_async16(dK + (uint32_t)(r*(QSTR*2) + c*16), kp + (size_t)r*DD + c*8);
            }
            for (int i = tid; i < 1024; i += 128) {
                int r = i >> 3, c = i & 7;
                cp_async16(dV + (uint32_t)(r*(VSTR*2) + c*16), vp + (size_t)r*SS + c*8);
            }
        }
        CP_COMMIT();
        CP_WAIT(1);
        __syncthreads();

        uint32_t cK = sK + (t&1) * AK_BYTES;
        uint32_t cV = sV + (t&1) * AV_BYTES;

        float s[8][4];
        #pragma unroll
        for (int j = 0; j < 8; j++)
            #pragma unroll
            for (int c = 0; c < 4; c++) s[j][c] = 0.f;

        #pragma unroll
        for (int kb = 0; kb < 8; kb++) {
            #pragma unroll
            for (int np = 0; np < 4; np++) {
                uint32_t r0, r1, r2, r3;
                ldsm4(cK + (uint32_t)((16*np + rowoff)*(QSTR*2) + kb*32 + kofs),
                      r0, r1, r2, r3);
                uint32_t b0[2] = {r0, r2}, b1[2] = {r1, r3};
                mma_f16(s[2*np],   qfr[kb], b0);
                mma_f16(s[2*np+1], qfr[kb], b1);
            }
        }

        if (t == qt) {
            int r0l = w*16 + g, r1l = r0l + 8;
            #pragma unroll
            for (int j = 0; j < 8; j++) {
                int c0 = 8*j + 2*tig;
                if (c0     > r0l) s[j][0] = -1e30f;
                if (c0 + 1 > r0l) s[j][1] = -1e30f;
                if (c0     > r1l) s[j][2] = -1e30f;
                if (c0 + 1 > r1l) s[j][3] = -1e30f;
            }
        }

        float tm0 = -1e30f, tm1 = -1e30f;
        #pragma unroll
        for (int j = 0; j < 8; j++) {
            tm0 = fmaxf(tm0, fmaxf(s[j][0], s[j][1]));
            tm1 = fmaxf(tm1, fmaxf(s[j][2], s[j][3]));
        }
        tm0 = fmaxf(tm0, __shfl_xor_sync(~0u, tm0, 1));
        tm0 = fmaxf(tm0, __shfl_xor_sync(~0u, tm0, 2));
        tm1 = fmaxf(tm1, __shfl_xor_sync(~0u, tm1, 1));
        tm1 = fmaxf(tm1, __shfl_xor_sync(~0u, tm1, 2));

        float mn0 = fmaxf(m0v, tm0), mn1 = fmaxf(m1v, tm1);
        float a0 = __expf(m0v - mn0), a1 = __expf(m1v - mn1);
        m0v = mn0; m1v = mn1;

        float ts0 = 0.f, ts1 = 0.f;
        #pragma unroll
        for (int j = 0; j < 8; j++) {
            s[j][0] = __expf(s[j][0] - mn0);
            s[j][1] = __expf(s[j][1] - mn0);
            s[j][2] = __expf(s[j][2] - mn1);
            s[j][3] = __expf(s[j][3] - mn1);
            ts0 += s[j][0] + s[j][1];
            ts1 += s[j][2] + s[j][3];
        }
        ts0 += __shfl_xor_sync(~0u, ts0, 1);
        ts0 += __shfl_xor_sync(~0u, ts0, 2);
        ts1 += __shfl_xor_sync(~0u, ts1, 1);
        ts1 += __shfl_xor_sync(~0u, ts1, 2);
        l0 = l0 * a0 + ts0;
        l1 = l1 * a1 + ts1;

        #pragma unroll
        for (int i = 0; i < 16; i++) {
            oac[i][0] *= a0; oac[i][1] *= a0;
            oac[i][2] *= a1; oac[i][3] *= a1;
        }

        uint32_t pf[4][4];
        #pragma unroll
        for (int jj = 0; jj < 4; jj++) {
            pf[jj][0] = h2pack(s[2*jj][0],   s[2*jj][1]);
            pf[jj][1] = h2pack(s[2*jj][2],   s[2*jj][3]);
            pf[jj][2] = h2pack(s[2*jj+1][0], s[2*jj+1][1]);
            pf[jj][3] = h2pack(s[2*jj+1][2], s[2*jj+1][3]);
        }

        #pragma unroll
        for (int jj = 0; jj < 4; jj++) {
            #pragma unroll
            for (int dp = 0; dp < 8; dp++) {
                uint32_t r0, r1, r2, r3;
                ldsm4(cV + (uint32_t)((16*dp + rowoff)*(VSTR*2) + jj*32 + kofs),
                      r0, r1, r2, r3);
                uint32_t b0[2] = {r0, r2}, b1[2] = {r1, r3};
                mma_f16(oac[2*dp],   pf[jj], b0);
                mma_f16(oac[2*dp+1], pf[jj], b1);
            }
        }
        __syncthreads();
    }

    float il0 = 1.f / l0, il1 = 1.f / l1;
    int r0g = q0 + w*16 + g;
    __half* ob0 = o + (size_t)(b*SS + r0g) * HH + h * DD;
    __half* ob1 = ob0 + (size_t)8 * HH;
    #pragma unroll
    for (int ntl = 0; ntl < 16; ntl++) {
        int d = 8*ntl + 2*tig;
        __half2 v0 = __floats2half2_rn(oac[ntl][0]*il0, oac[ntl][1]*il0);
        __half2 v1 = __floats2half2_rn(oac[ntl][2]*il1, oac[ntl][3]*il1);
        *(__half2*)(ob0 + d) = v0;
        *(__half2*)(ob1 + d) = v1;
    }
}

// ================= launch =================
extern "C" void kernel_launch(void* const* d_in, const int* in_sizes, int n_in,
                              void* d_out, int out_size) {
    const float* x     = (const float*)d_in[0];
    const float* cosT  = (const float*)d_in[1];
    const float* sinT  = (const float*)d_in[2];
    const float* anw   = (const float*)d_in[3];
    const float* fnw   = (const float*)d_in[4];
    const float* wq    = (const float*)d_in[5];
    const float* wk    = (const float*)d_in[6];
    const float* wv    = (const float*)d_in[7];
    const float* wo    = (const float*)d_in[8];
    const float* wgate = (const float*)d_in[9];
    const float* wup   = (const float*)d_in[10];
    const float* wdown = (const float*)d_in[11];
    float* out = (float*)d_out;

    __half *p_hin, *p_qkv, *p_qh, *p_kh, *p_vt, *p_attn, *p_ffn, *p_wqkv, *p_wo, *p_wgu, *p_wd;
    float *p_h;
    cudaGetSymbolAddress((void**)&p_hin,  g_hin);
    cudaGetSymbolAddress((void**)&p_qkv,  g_qkv);
    cudaGetSymbolAddress((void**)&p_qh,   g_qh);
    cudaGetSymbolAddress((void**)&p_kh,   g_kh);
    cudaGetSymbolAddress((void**)&p_vt,   g_vt);
    cudaGetSymbolAddress((void**)&p_attn, g_attn);
    cudaGetSymbolAddress((void**)&p_h,    g_h);
    cudaGetSymbolAddress((void**)&p_ffn,  g_ffn);
    cudaGetSymbolAddress((void**)&p_wqkv, g_wqkv);
    cudaGetSymbolAddress((void**)&p_wo,   g_wo_t);
    cudaGetSymbolAddress((void**)&p_wgu,  g_wgu);
    cudaGetSymbolAddress((void**)&p_wd,   g_wd_t);

    cudaFuncSetAttribute(hgemm<0>, cudaFuncAttributeMaxDynamicSharedMemorySize, SMEM_BYTES);
    cudaFuncSetAttribute(hgemm<1>, cudaFuncAttributeMaxDynamicSharedMemorySize, SMEM_BYTES);
    cudaFuncSetAttribute(hgemm<2>, cudaFuncAttributeMaxDynamicSharedMemorySize, SMEM_BYTES);
    cudaFuncSetAttribute(hgemm<3>, cudaFuncAttributeMaxDynamicSharedMemorySize, SMEM_BYTES);
    cudaFuncSetAttribute(fattn,    cudaFuncAttributeMaxDynamicSharedMemorySize, ATT_SMEM);

    // 0) attn rmsnorm -> half
    rmsnorm_kernel<<<TT, 256>>>(x, anw, p_hin);
    // 1-4) qkv + wo weight packs
    pack64<<<dim3(HH/64, HH/64), 256>>>(wq, p_wqkv, HH, HH, 1, 0);
    pack64<<<dim3(HH/64, (NKV*DD)/64), 256>>>(wk, p_wqkv + (size_t)HH*HH, HH, NKV*DD, 1, 0);
    pack64<<<dim3(HH/64, (NKV*DD)/64), 256>>>(wv, p_wqkv + (size_t)(HH+NKV*DD)*HH, HH, NKV*DD, 1, 0);
    pack64<<<dim3(HH/64, HH/64), 256>>>(wo, p_wo, HH, HH, 1, 0);
    // 5) fused qkv projection -> half
    hgemm<3><<<dim3(TT/BM, QKV_N/BN), 256, SMEM_BYTES>>>(p_hin, p_wqkv, nullptr, p_qkv, TT, QKV_N, HH);
    // 6-8) ffn weight packs (interleaved gate/up; down)
    pack64<<<dim3(HH/64, II/64), 256>>>(wgate, p_wgu, HH, II, 2, 0);
    pack64<<<dim3(HH/64, II/64), 256>>>(wup,   p_wgu, HH, II, 2, 1);
    pack64<<<dim3(II/64, HH/64), 256>>>(wdown, p_wd, II, HH, 1, 0);
    // 9-10) RoPE + extract into attention layouts
    {
        int tqk = TT * (NQ + NKV) * 64;
        rope_qk<<<(tqk + 255) / 256, 256>>>(p_qkv, cosT, sinT, p_qh, p_kh);
        dim3 tb(32, 8);
        v_trans<<<dim3(SS/32, DD/32, BB*NKV), tb>>>(p_qkv, p_vt);
    }
    // 11) flash attention -> half [b,s,h,d]
    fattn<<<dim3(SS/AQT, NQ, BB), 128, ATT_SMEM>>>(p_qh, p_kh, p_vt, p_attn);
    // 12) output projection + residual: h = x + attn @ wo
    hgemm<1><<<dim3(TT/BM, HH/BN), 256, SMEM_BYTES>>>(p_attn, p_wo, x, p_h, TT, HH, HH);
    // 13) ffn rmsnorm -> half
    rmsnorm_kernel<<<TT, 256>>>(p_h, fnw, p_hin);
    // 14) fused gate+up with silu epilogue -> half [TT][II]
    hgemm<2><<<dim3(TT/BM, GU_N/BN), 256, SMEM_BYTES>>>(p_hin, p_wgu, nullptr, p_ffn, TT, GU_N, HH);
    // 15) down projection + residual: out = h + ffn @ wdown
    hgemm<1><<<dim3(TT/BM, HH/BN), 256, SMEM_BYTES>>>(p_ffn, p_wd, p_h, out, TT, HH, II);
}

// round 14
// speedup vs baseline: 1.1870x; 1.1251x over previous
#include <cuda_runtime.h>
#include <cuda_fp16.h>
#include <cstdint>
#include <math.h>

// ---------------- problem constants ----------------
#define BB 2
#define SS 1024
#define HH 4096
#define NQ 32
#define NKV 8
#define DD 128
#define II 11008
#define TT (BB*SS)          // 2048 tokens
#define EPS 1e-5f

#define QKV_N (HH + 2*NKV*DD)   // 6144
#define GU_N  (2*II)            // 22016 (8-col-block interleaved gate/up)

// ---------------- scratch (device globals, no allocation) ----------------
__device__ __half g_hin  [(size_t)TT*HH];
__device__ __half g_qkv  [(size_t)TT*QKV_N];
__device__ __half g_qh   [(size_t)TT*NQ*DD];
__device__ __half g_kh   [(size_t)TT*NKV*DD];
__device__ __half g_vt   [(size_t)TT*NKV*DD];
__device__ __half g_attn [(size_t)TT*HH];
__device__ float  g_h    [(size_t)TT*HH];
__device__ __half g_ffn  [(size_t)TT*II];
__device__ __half g_wqkv [(size_t)HH*QKV_N];   // [K=4096][6144] half (no transpose)
__device__ __half g_wo_h [(size_t)HH*HH];      // [K][N]
__device__ __half g_wgu  [(size_t)HH*GU_N];    // [K][2I], 8-col blocks interleaved
__device__ __half g_wd_h [(size_t)II*HH];      // [K=11008][4096]

// ================= helpers =================
__device__ __forceinline__ uint32_t smem_u32(const void* p) {
    uint32_t a;
    asm("{ .reg .u64 t; cvta.to.shared.u64 t, %1; cvt.u32.u64 %0, t; }" : "=r"(a) : "l"(p));
    return a;
}
__device__ __forceinline__ void cp_async16(uint32_t dst, const void* src) {
    asm volatile("cp.async.cg.shared.global [%0], [%1], 16;" :: "r"(dst), "l"(src));
}
#define CP_COMMIT() asm volatile("cp.async.commit_group;" ::: "memory")
#define CP_WAIT(n)  asm volatile("cp.async.wait_group %0;" :: "n"(n) : "memory")

__device__ __forceinline__ void ldsm4(uint32_t addr, uint32_t& r0, uint32_t& r1,
                                      uint32_t& r2, uint32_t& r3) {
    asm volatile("ldmatrix.sync.aligned.m8n8.x4.shared.b16 {%0,%1,%2,%3}, [%4];"
                 : "=r"(r0), "=r"(r1), "=r"(r2), "=r"(r3) : "r"(addr));
}
__device__ __forceinline__ void ldsm4t(uint32_t addr, uint32_t& r0, uint32_t& r1,
                                       uint32_t& r2, uint32_t& r3) {
    asm volatile("ldmatrix.sync.aligned.m8n8.x4.trans.shared.b16 {%0,%1,%2,%3}, [%4];"
                 : "=r"(r0), "=r"(r1), "=r"(r2), "=r"(r3) : "r"(addr));
}
__device__ __forceinline__ void mma_f16(float* d, const uint32_t* a, const uint32_t* b) {
    asm volatile(
        "mma.sync.aligned.m16n8k16.row.col.f32.f16.f16.f32 "
        "{%0,%1,%2,%3}, {%4,%5,%6,%7}, {%8,%9}, {%0,%1,%2,%3};\n"
        : "+f"(d[0]), "+f"(d[1]), "+f"(d[2]), "+f"(d[3])
        : "r"(a[0]), "r"(a[1]), "r"(a[2]), "r"(a[3]), "r"(b[0]), "r"(b[1]));
}
__device__ __forceinline__ uint32_t h2pack(float a, float b) {
    __half2 h = __floats2half2_rn(a, b);
    return *(uint32_t*)&h;
}

// ================= fp16 tensor-core GEMM (NT: B = [K][N] row-major) ==========
// C[M,N] = A[M,K] @ B[K,N]. CTA tile 128x128, BK=64, 3-stage cp.async,
// 8 warps (2m x 4n), warp 64x32, 2 CTAs/SM. Single-sync mainloop.
// A tile: [128 m][64 k] padded rows (TN side unchanged).
// B tile: [64 k][128 n] padded rows; fragments via ldmatrix.trans.
// EPI 0: C = acc (fp32). EPI 1: C = res + acc (fp32).
// EPI 2: Chalf[M][N/2] = silu(gate)*up, gate/up interleaved in 8-col blocks.
// EPI 3: Chalf = acc.
#define BM 128
#define BN 128
#define BK 64
#define STAGES 3
#define AROWB 144                         // A row: 64 halves + 16B pad
#define BROWB 272                         // B row: 128 halves + 16B pad
#define A_TILEB (128*AROWB)               // 18432
#define B_TILEB (64*BROWB)                // 17408
#define STAGE_B (A_TILEB + B_TILEB)       // 35840
#define SMEM_BYTES (STAGES*STAGE_B)       // 107520

__device__ __forceinline__ void load_stage(uint32_t sb, int st,
                                           const __half* __restrict__ A,
                                           const __half* __restrict__ B,
                                           int m0, int n0, int k0, int K, int N) {
    int t = threadIdx.x;
    uint32_t sA = sb + st * STAGE_B;
    uint32_t sB = sA + A_TILEB;
    #pragma unroll
    for (int i = 0; i < 4; i++) {                 // A: 128 m-rows x 8 chunks
        int c = t + i * 256;
        int row = c >> 3, ch = c & 7;
        cp_async16(sA + (uint32_t)(row * AROWB + ch * 16),
                   A + (size_t)(m0 + row) * K + k0 + ch * 8);
    }
    #pragma unroll
    for (int i = 0; i < 4; i++) {                 // B: 64 k-rows x 16 chunks
        int c = t + i * 256;
        int row = c >> 4, ch = c & 15;
        cp_async16(sB + (uint32_t)(row * BROWB + ch * 16),
                   B + (size_t)(k0 + row) * N + n0 + ch * 8);
    }
}

template<int EPI>
__global__ void __launch_bounds__(256, 2)
hgemm(const __half* __restrict__ A, const __half* __restrict__ B,
      const float* __restrict__ res, void* __restrict__ Cout,
      int M, int N, int K) {
    extern __shared__ char smem[];
    uint32_t sb = smem_u32(smem);
    int tid = threadIdx.x, wid = tid >> 5, lane = tid & 31;
    int wm = wid >> 2, wn = wid & 3;
    int group = lane >> 2, tig = lane & 3;
    int m0 = blockIdx.x * BM, n0 = blockIdx.y * BN;

    int rowoff  = (lane & 7) + ((lane >> 3) & 1) * 8;   // A-side ldsm rows
    int koff    = (lane >> 4) * 16;                     // A-side k-byte offset
    int browoff = (lane & 7) + ((lane >> 3) & 1) * 8;   // B-side k rows
    int bnoff   = (lane >> 4) * 8;                      // B-side n offset

    float acc[4][4][4];
    #pragma unroll
    for (int mt = 0; mt < 4; mt++)
        #pragma unroll
        for (int nt = 0; nt < 4; nt++)
            #pragma unroll
            for (int j = 0; j < 4; j++) acc[mt][nt][j] = 0.f;

    int nk = K / BK;
    #pragma unroll
    for (int s = 0; s < STAGES - 1; s++) {
        load_stage(sb, s, A, B, m0, n0, s * BK, K, N);
        CP_COMMIT();
    }

    int st = 0;
    for (int kt = 0; kt < nk; kt++) {
        CP_WAIT(STAGES - 2);
        __syncthreads();

        int nxt = kt + STAGES - 1;
        if (nxt < nk) {
            int nst = st + (STAGES - 1); if (nst >= STAGES) nst -= STAGES;
            load_stage(sb, nst, A, B, m0, n0, nxt * BK, K, N);
        }
        CP_COMMIT();

        uint32_t sA = sb + st * STAGE_B;
        uint32_t sB = sA + A_TILEB;

        #pragma unroll
        for (int ks = 0; ks < 4; ks++) {
            uint32_t a[4][4], bfr[4][2];
            #pragma unroll
            for (int mt = 0; mt < 4; mt++) {
                uint32_t ad = sA + (uint32_t)((wm * 64 + mt * 16 + rowoff) * AROWB + ks * 32 + koff);
                ldsm4(ad, a[mt][0], a[mt][1], a[mt][2], a[mt][3]);
            }
            #pragma unroll
            for (int np = 0; np < 2; np++) {
                uint32_t bd = sB + (uint32_t)((ks * 16 + browoff) * BROWB
                                              + (wn * 32 + np * 16 + bnoff) * 2);
                uint32_t r0, r1, r2, r3;
                ldsm4t(bd, r0, r1, r2, r3);
                bfr[2*np][0]   = r0; bfr[2*np][1]   = r1;   // n-lo: k-lo, k-hi
                bfr[2*np+1][0] = r2; bfr[2*np+1][1] = r3;   // n-hi
            }
            #pragma unroll
            for (int mt = 0; mt < 4; mt++)
                #pragma unroll
                for (int nt = 0; nt < 4; nt++)
                    mma_f16(acc[mt][nt], a[mt], bfr[nt]);
        }
        if (++st == STAGES) st = 0;
    }

    // epilogue
    if (EPI == 2) {
        __half* Ch = (__half*)Cout;
        int No = N >> 1;
        #pragma unroll
        for (int mt = 0; mt < 4; mt++) {
            int r0 = m0 + wm * 64 + mt * 16 + group;
            #pragma unroll
            for (int a = 0; a < 2; a++) {
                // nt=2a holds gate cols, nt=2a+1 holds up cols of same logical j
                int base = n0 + wn * 32 + 16 * a;
                int j = (base >> 1) + 2 * tig;
                float g0 = acc[mt][2*a][0],  g0b = acc[mt][2*a][1];
                float u0 = acc[mt][2*a+1][0], u0b = acc[mt][2*a+1][1];
                float g1 = acc[mt][2*a][2],  g1b = acc[mt][2*a][3];
                float u1 = acc[mt][2*a+1][2], u1b = acc[mt][2*a+1][3];
                __half2 w0 = __floats2half2_rn(g0 / (1.f + __expf(-g0)) * u0,
                                               g0b / (1.f + __expf(-g0b)) * u0b);
                __half2 w1 = __floats2half2_rn(g1 / (1.f + __expf(-g1)) * u1,
                                               g1b / (1.f + __expf(-g1b)) * u1b);
                *(__half2*)(Ch + (size_t)r0 * No + j)       = w0;
                *(__half2*)(Ch + (size_t)(r0 + 8) * No + j) = w1;
            }
        }
    } else {
        #pragma unroll
        for (int mt = 0; mt < 4; mt++) {
            int r0 = m0 + wm * 64 + mt * 16 + group;
            #pragma unroll
            for (int nt = 0; nt < 4; nt++) {
                int c = n0 + wn * 32 + nt * 8 + 2 * tig;
                if (EPI == 3) {
                    __half* Ch = (__half*)Cout;
                    size_t i0 = (size_t)r0 * N + c;
                    size_t i1 = (size_t)(r0 + 8) * N + c;
                    *(__half2*)(Ch + i0) = __floats2half2_rn(acc[mt][nt][0], acc[mt][nt][1]);
                    *(__half2*)(Ch + i1) = __floats2half2_rn(acc[mt][nt][2], acc[mt][nt][3]);
                } else {
                    float* C = (float*)Cout;
                    size_t i0 = (size_t)r0 * N + c;
                    size_t i1 = (size_t)(r0 + 8) * N + c;
                    float2 v0 = make_float2(acc[mt][nt][0], acc[mt][nt][1]);
                    float2 v1 = make_float2(acc[mt][nt][2], acc[mt][nt][3]);
                    if (EPI == 1) {
                        float2 r0v = *(const float2*)(res + i0);
                        float2 r1v = *(const float2*)(res + i1);
                        v0.x += r0v.x; v0.y += r0v.y;
                        v1.x += r1v.x; v1.y += r1v.y;
                    }
                    *(float2*)(C + i0) = v0;
                    *(float2*)(C + i1) = v1;
                }
            }
        }
    }
}

// ================= streaming converts (no transpose) =================
// W[K][N] fp32 -> Wh[K][dstN] half at column offset; 8 floats per thread.
__global__ void conv_h(const float* __restrict__ W, __half* __restrict__ Wh,
                       int N, int dstN, long colOff, long total8) {
    long i = (long)blockIdx.x * 256 + threadIdx.x;
    if (i >= total8) return;
    int n8 = N >> 3;
    long row = i / n8;
    int c = (int)(i - row * n8) * 8;
    const float* src = W + row * (size_t)N + c;
    float4 v0 = *(const float4*)src;
    float4 v1 = *(const float4*)(src + 4);
    uint4 o;
    o.x = h2pack(v0.x, v0.y); o.y = h2pack(v0.z, v0.w);
    o.z = h2pack(v1.x, v1.y); o.w = h2pack(v1.z, v1.w);
    *(uint4*)(Wh + row * (size_t)dstN + colOff + c) = o;
}

// gate[K][I], up[K][I] -> wgu[K][2I], 8-col blocks interleaved:
// cols [16a..16a+7] = gate[8a..8a+7], cols [16a+8..16a+15] = up[8a..8a+7].
__global__ void conv_gu(const float* __restrict__ G, const float* __restrict__ U,
                        __half* __restrict__ Wt, long total) {
    long i = (long)blockIdx.x * 256 + threadIdx.x;
    if (i >= total) return;                 // total = K * (I/8)
    int nb = II >> 3;
    long k = i / nb;
    int a = (int)(i - k * nb);
    const float* gp = G + k * (size_t)II + a * 8;
    const float* up = U + k * (size_t)II + a * 8;
    float4 g0 = *(const float4*)gp,      g1 = *(const float4*)(gp + 4);
    float4 u0 = *(const float4*)up,      u1 = *(const float4*)(up + 4);
    uint4 w0, w1;
    w0.x = h2pack(g0.x, g0.y); w0.y = h2pack(g0.z, g0.w);
    w0.z = h2pack(g1.x, g1.y); w0.w = h2pack(g1.z, g1.w);
    w1.x = h2pack(u0.x, u0.y); w1.y = h2pack(u0.z, u0.w);
    w1.z = h2pack(u1.x, u1.y); w1.w = h2pack(u1.z, u1.w);
    __half* d = Wt + k * (size_t)GU_N + a * 16;
    *(uint4*)d       = w0;
    *(uint4*)(d + 8) = w1;
}

// ================= rmsnorm (half output) =================
__global__ void rmsnorm_kernel(const float* __restrict__ x,
                               const float* __restrict__ w,
                               __half* __restrict__ out) {
    int row = blockIdx.x;
    const float* xr = x + (size_t)row * HH;
    float ss = 0.f;
    for (int i = threadIdx.x; i < HH; i += blockDim.x) {
        float v = xr[i];
        ss = fmaf(v, v, ss);
    }
    __shared__ float red[32];
    int lane = threadIdx.x & 31, warp = threadIdx.x >> 5;
    #pragma unroll
    for (int off = 16; off; off >>= 1) ss += __shfl_xor_sync(~0u, ss, off);
    if (lane == 0) red[warp] = ss;
    __syncthreads();
    int nwarp = blockDim.x >> 5;
    if (warp == 0) {
        float v = (lane < nwarp) ? red[lane] : 0.f;
        #pragma unroll
        for (int off = 16; off; off >>= 1) v += __shfl_xor_sync(~0u, v, off);
        if (lane == 0) red[0] = v;
    }
    __syncthreads();
    float inv = rsqrtf(red[0] / (float)HH + EPS);
    __half* orow = out + (size_t)row * HH;
    for (int i = threadIdx.x; i < HH; i += blockDim.x)
        orow[i] = __float2half_rn(xr[i] * inv * w[i]);
}

// ================= fused RoPE extract: q (scaled) + k =================
__global__ void rope_qk(const __half* __restrict__ qkv,
                        const float* __restrict__ cosT,
                        const float* __restrict__ sinT,
                        __half* __restrict__ qh,
                        __half* __restrict__ kh) {
    int idx = blockIdx.x * blockDim.x + threadIdx.x;
    if (idx >= TT * (NQ + NKV) * 64) return;
    const float qscale = 0.08838834764831845f;
    int d  = idx & 63;
    int hh = (idx >> 6) % (NQ + NKV);
    int t  = idx / (64 * (NQ + NKV));
    int s  = t % SS, b = t / SS;
    float c1 = cosT[s*DD + d],      s1 = sinT[s*DD + d];
    float c2 = cosT[s*DD + d + 64], s2 = sinT[s*DD + d + 64];
    if (hh < NQ) {
        const __half* p = qkv + (size_t)t * QKV_N + hh * DD;
        float x1 = __half2float(p[d]), x2 = __half2float(p[d + 64]);
        size_t row = ((size_t)(b*NQ + hh)*SS + s) * DD;
        qh[row + d]      = __float2half_rn((x1 * c1 - x2 * s1) * qscale);
        qh[row + d + 64] = __float2half_rn((x2 * c2 + x1 * s2) * qscale);
    } else {
        int h = hh - NQ;
        const __half* p = qkv + (size_t)t * QKV_N + HH + h * DD;
        float x1 = __half2float(p[d]), x2 = __half2float(p[d + 64]);
        size_t row = ((size_t)(b*NKV + h)*SS + s) * DD;
        kh[row + d]      = __float2half_rn(x1 * c1 - x2 * s1);
        kh[row + d + 64] = __float2half_rn(x2 * c2 + x1 * s2);
    }
}

// ================= V extract + transpose: vt[b,kvh,d,s] =================
__global__ void v_trans(const __half* __restrict__ qkv, __half* __restrict__ vt) {
    __shared__ __half tile[32][33];
    int s0 = blockIdx.x * 32, d0 = blockIdx.y * 32;
    int bk = blockIdx.z;
    int b = bk / NKV, kvh = bk % NKV;
    int tx = threadIdx.x, ty = threadIdx.y;
    #pragma unroll
    for (int i = 0; i < 32; i += 8) {
        int s = s0 + ty + i;
        tile[ty + i][tx] = qkv[(size_t)(b*SS + s) * QKV_N + HH + NKV*DD + kvh*DD + d0 + tx];
    }
    __syncthreads();
    #pragma unroll
    for (int i = 0; i < 32; i += 8)
        vt[((size_t)(b*NKV + kvh)*DD + d0 + ty + i) * SS + s0 + tx] = tile[tx][ty + i];
}

// ================= fp16 flash attention (unchanged) =================
#define AQT 64
#define AKT 64
#define QSTR 136
#define VSTR 72
#define AQ_BYTES (AQT*QSTR*2)
#define AK_BYTES (AKT*QSTR*2)
#define AV_BYTES (DD*VSTR*2)
#define ATT_SMEM (AQ_BYTES + 2*AK_BYTES + 2*AV_BYTES)

__global__ void __launch_bounds__(128, 2)
fattn(const __half* __restrict__ qh, const __half* __restrict__ kh,
      const __half* __restrict__ vt, __half* __restrict__ o) {
    extern __shared__ char sm[];
    uint32_t sb = smem_u32(sm);
    uint32_t sQ = sb;
    uint32_t sK = sQ + AQ_BYTES;
    uint32_t sV = sK + 2*AK_BYTES;

    int b = blockIdx.z, h = blockIdx.y;
    int qt = gridDim.x - 1 - blockIdx.x;
    int kvh = h >> 2;
    int q0 = qt * AQT;
    int tid = threadIdx.x, w = tid >> 5, lane = tid & 31;
    int g = lane >> 2, tig = lane & 3;
    int rowoff = lane & 15;
    int kofs   = (lane >> 4) * 16;

    const __half* qbase = qh + ((size_t)(b*NQ + h)*SS + q0) * DD;
    const __half* kbase = kh + ((size_t)(b*NKV + kvh)*SS) * DD;
    const __half* vbase = vt + ((size_t)(b*NKV + kvh)*DD) * SS;

    for (int i = tid; i < 1024; i += 128) {
        int r = i >> 4, c = i & 15;
        cp_async16(sQ + (uint32_t)(r*(QSTR*2) + c*16), qbase + (size_t)r*DD + c*8);
    }
    CP_COMMIT();

    int nt = qt + 1;
    {
        uint32_t dK = sK, dV = sV;
        for (int i = tid; i < 1024; i += 128) {
            int r = i >> 4, c = i & 15;
            cp_async16(dK + (uint32_t)(r*(QSTR*2) + c*16), kbase + (size_t)r*DD + c*8);
        }
        for (int i = tid; i < 1024; i += 128) {
            int r = i >> 3, c = i & 7;
            cp_async16(dV + (uint32_t)(r*(VSTR*2) + c*16), vbase + (size_t)r*SS + c*8);
        }
    }
    CP_COMMIT();

    CP_WAIT(1);
    __syncthreads();
    uint32_t qfr[8][4];
    #pragma unroll
    for (int kb = 0; kb < 8; kb++)
        ldsm4(sQ + (uint32_t)((w*16 + rowoff)*(QSTR*2) + kb*32 + kofs),
              qfr[kb][0], qfr[kb][1], qfr[kb][2], qfr[kb][3]);

    float m0v = -INFINITY, m1v = -INFINITY, l0 = 0.f, l1 = 0.f;
    float oac[16][4];
    #pragma unroll
    for (int i = 0; i < 16; i++)
        #pragma unroll
        for (int j = 0; j < 4; j++) oac[i][j] = 0.f;

    for (int t = 0; t < nt; t++) {
        if (t + 1 < nt) {
            uint32_t dK = sK + ((t+1)&1) * AK_BYTES;
            uint32_t dV = sV + ((t+1)&1) * AV_BYTES;
            const __half* kp = kbase + (size_t)(t+1)*AKT*DD;
            const __half* vp = vbase + (t+1)*AKT;
            for (int i = tid; i < 1024; i += 128) {
                int r = i >> 4, c = i & 15;
                cp_async16(dK + (uint32_t)(r*(QSTR*2) + c*16), kp + (size_t)r*DD + c*8);
            }
            for (int i = tid; i < 1024; i += 128) {
                int r = i >> 3, c = i & 7;
                cp_async16(dV + (uint32_t)(r*(VSTR*2) + c*16), vp + (size_t)r*SS + c*8);
            }
        }
        CP_COMMIT();
        CP_WAIT(1);
        __syncthreads();

        uint32_t cK = sK + (t&1) * AK_BYTES;
        uint32_t cV = sV + (t&1) * AV_BYTES;

        float s[8][4];
        #pragma unroll
        for (int j = 0; j < 8; j++)
            #pragma unroll
            for (int c = 0; c < 4; c++) s[j][c] = 0.f;

        #pragma unroll
        for (int kb = 0; kb < 8; kb++) {
            #pragma unroll
            for (int np = 0; np < 4; np++) {
                uint32_t r0, r1, r2, r3;
                ldsm4(cK + (uint32_t)((16*np + rowoff)*(QSTR*2) + kb*32 + kofs),
                      r0, r1, r2, r3);
                uint32_t b0[2] = {r0, r2}, b1[2] = {r1, r3};
                mma_f16(s[2*np],   qfr[kb], b0);
                mma_f16(s[2*np+1], qfr[kb], b1);
            }
        }

        if (t == qt) {
            int r0l = w*16 + g, r1l = r0l + 8;
            #pragma unroll
            for (int j = 0; j < 8; j++) {
                int c0 = 8*j + 2*tig;
                if (c0     > r0l) s[j][0] = -1e30f;
                if (c0 + 1 > r0l) s[j][1] = -1e30f;
                if (c0     > r1l) s[j][2] = -1e30f;
                if (c0 + 1 > r1l) s[j][3] = -1e30f;
            }
        }

        float tm0 = -1e30f, tm1 = -1e30f;
        #pragma unroll
        for (int j = 0; j < 8; j++) {
            tm0 = fmaxf(tm0, fmaxf(s[j][0], s[j][1]));
            tm1 = fmaxf(tm1, fmaxf(s[j][2], s[j][3]));
        }
        tm0 = fmaxf(tm0, __shfl_xor_sync(~0u, tm0, 1));
        tm0 = fmaxf(tm0, __shfl_xor_sync(~0u, tm0, 2));
        tm1 = fmaxf(tm1, __shfl_xor_sync(~0u, tm1, 1));
        tm1 = fmaxf(tm1, __shfl_xor_sync(~0u, tm1, 2));

        float mn0 = fmaxf(m0v, tm0), mn1 = fmaxf(m1v, tm1);
        float a0 = __expf(m0v - mn0), a1 = __expf(m1v - mn1);
        m0v = mn0; m1v = mn1;

        float ts0 = 0.f, ts1 = 0.f;
        #pragma unroll
        for (int j = 0; j < 8; j++) {
            s[j][0] = __expf(s[j][0] - mn0);
            s[j][1] = __expf(s[j][1] - mn0);
            s[j][2] = __expf(s[j][2] - mn1);
            s[j][3] = __expf(s[j][3] - mn1);
            ts0 += s[j][0] + s[j][1];
            ts1 += s[j][2] + s[j][3];
        }
        ts0 += __shfl_xor_sync(~0u, ts0, 1);
        ts0 += __shfl_xor_sync(~0u, ts0, 2);
        ts1 += __shfl_xor_sync(~0u, ts1, 1);
        ts1 += __shfl_xor_sync(~0u, ts1, 2);
        l0 = l0 * a0 + ts0;
        l1 = l1 * a1 + ts1;

        #pragma unroll
        for (int i = 0; i < 16; i++) {
            oac[i][0] *= a0; oac[i][1] *= a0;
            oac[i][2] *= a1; oac[i][3] *= a1;
        }

        uint32_t pf[4][4];
        #pragma unroll
        for (int jj = 0; jj < 4; jj++) {
            pf[jj][0] = h2pack(s[2*jj][0],   s[2*jj][1]);
            pf[jj][1] = h2pack(s[2*jj][2],   s[2*jj][3]);
            pf[jj][2] = h2pack(s[2*jj+1][0], s[2*jj+1][1]);
            pf[jj][3] = h2pack(s[2*jj+1][2], s[2*jj+1][3]);
        }

        #pragma unroll
        for (int jj = 0; jj < 4; jj++) {
            #pragma unroll
            for (int dp = 0; dp < 8; dp++) {
                uint32_t r0, r1, r2, r3;
                ldsm4(cV + (uint32_t)((16*dp + rowoff)*(VSTR*2) + jj*32 + kofs),
                      r0, r1, r2, r3);
                uint32_t b0[2] = {r0, r2}, b1[2] = {r1, r3};
                mma_f16(oac[2*dp],   pf[jj], b0);
                mma_f16(oac[2*dp+1], pf[jj], b1);
            }
        }
        __syncthreads();
    }

    float il0 = 1.f / l0, il1 = 1.f / l1;
    int r0g = q0 + w*16 + g;
    __half* ob0 = o + (size_t)(b*SS + r0g) * HH + h * DD;
    __half* ob1 = ob0 + (size_t)8 * HH;
    #pragma unroll
    for (int ntl = 0; ntl < 16; ntl++) {
        int d = 8*ntl + 2*tig;
        __half2 v0 = __floats2half2_rn(oac[ntl][0]*il0, oac[ntl][1]*il0);
        __half2 v1 = __floats2half2_rn(oac[ntl][2]*il1, oac[ntl][3]*il1);
        *(__half2*)(ob0 + d) = v0;
        *(__half2*)(ob1 + d) = v1;
    }
}

// ================= launch =================
extern "C" void kernel_launch(void* const* d_in, const int* in_sizes, int n_in,
                              void* d_out, int out_size) {
    const float* x     = (const float*)d_in[0];
    const float* cosT  = (const float*)d_in[1];
    const float* sinT  = (const float*)d_in[2];
    const float* anw   = (const float*)d_in[3];
    const float* fnw   = (const float*)d_in[4];
    const float* wq    = (const float*)d_in[5];
    const float* wk    = (const float*)d_in[6];
    const float* wv    = (const float*)d_in[7];
    const float* wo    = (const float*)d_in[8];
    const float* wgate = (const float*)d_in[9];
    const float* wup   = (const float*)d_in[10];
    const float* wdown = (const float*)d_in[11];
    float* out = (float*)d_out;

    __half *p_hin, *p_qkv, *p_qh, *p_kh, *p_vt, *p_attn, *p_ffn, *p_wqkv, *p_wo, *p_wgu, *p_wd;
    float *p_h;
    cudaGetSymbolAddress((void**)&p_hin,  g_hin);
    cudaGetSymbolAddress((void**)&p_qkv,  g_qkv);
    cudaGetSymbolAddress((void**)&p_qh,   g_qh);
    cudaGetSymbolAddress((void**)&p_kh,   g_kh);
    cudaGetSymbolAddress((void**)&p_vt,   g_vt);
    cudaGetSymbolAddress((void**)&p_attn, g_attn);
    cudaGetSymbolAddress((void**)&p_h,    g_h);
    cudaGetSymbolAddress((void**)&p_ffn,  g_ffn);
    cudaGetSymbolAddress((void**)&p_wqkv, g_wqkv);
    cudaGetSymbolAddress((void**)&p_wo,   g_wo_h);
    cudaGetSymbolAddress((void**)&p_wgu,  g_wgu);
    cudaGetSymbolAddress((void**)&p_wd,   g_wd_h);

    cudaFuncSetAttribute(hgemm<0>, cudaFuncAttributeMaxDynamicSharedMemorySize, SMEM_BYTES);
    cudaFuncSetAttribute(hgemm<1>, cudaFuncAttributeMaxDynamicSharedMemorySize, SMEM_BYTES);
    cudaFuncSetAttribute(hgemm<2>, cudaFuncAttributeMaxDynamicSharedMemorySize, SMEM_BYTES);
    cudaFuncSetAttribute(hgemm<3>, cudaFuncAttributeMaxDynamicSharedMemorySize, SMEM_BYTES);
    cudaFuncSetAttribute(fattn,    cudaFuncAttributeMaxDynamicSharedMemorySize, ATT_SMEM);

    // 0) attn rmsnorm -> half
    rmsnorm_kernel<<<TT, 256>>>(x, anw, p_hin);
    // 1-4) streaming weight converts for qkv + wo
    {
        long t8;
        t8 = (long)HH*HH/8;
        conv_h<<<(unsigned)((t8+255)/256), 256>>>(wq, p_wqkv, HH, QKV_N, 0, t8);
        t8 = (long)HH*(NKV*DD)/8;
        conv_h<<<(unsigned)((t8+255)/256), 256>>>(wk, p_wqkv, NKV*DD, QKV_N, HH, t8);
        conv_h<<<(unsigned)((t8+255)/256), 256>>>(wv, p_wqkv, NKV*DD, QKV_N, HH+NKV*DD, t8);
        t8 = (long)HH*HH/8;
        conv_h<<<(unsigned)((t8+255)/256), 256>>>(wo, p_wo, HH, HH, 0, t8);
    }
    // 5) fused qkv projection -> half
    hgemm<3><<<dim3(TT/BM, QKV_N/BN), 256, SMEM_BYTES>>>(p_hin, p_wqkv, nullptr, p_qkv, TT, QKV_N, HH);
    // 6-7) ffn weight converts (interleaved gate/up; down)
    {
        long tg = (long)HH * (II/8);
        conv_gu<<<(unsigned)((tg+255)/256), 256>>>(wgate, wup, p_wgu, tg);
        long t8 = (long)II*HH/8;
        conv_h<<<(unsigned)((t8+255)/256), 256>>>(wdown, p_wd, HH, HH, 0, t8);
    }
    // 8-9) RoPE + extract into attention layouts
    {
        int tqk = TT * (NQ + NKV) * 64;
        rope_qk<<<(tqk + 255) / 256, 256>>>(p_qkv, cosT, sinT, p_qh, p_kh);
        dim3 tb(32, 8);
        v_trans<<<dim3(SS/32, DD/32, BB*NKV), tb>>>(p_qkv, p_vt);
    }
    // 10) flash attention -> half [b,s,h,d]
    fattn<<<dim3(SS/AQT, NQ, BB), 128, ATT_SMEM>>>(p_qh, p_kh, p_vt, p_attn);
    // 11) output projection + residual: h = x + attn @ wo
    hgemm<1><<<dim3(TT/BM, HH/BN), 256, SMEM_BYTES>>>(p_attn, p_wo, x, p_h, TT, HH, HH);
    // 12) ffn rmsnorm -> half
    rmsnorm_kernel<<<TT, 256>>>(p_h, fnw, p_hin);
    // 13) fused gate+up with silu epilogue -> half [TT][II]
    hgemm<2><<<dim3(TT/BM, GU_N/BN), 256, SMEM_BYTES>>>(p_hin, p_wgu, nullptr, p_ffn, TT, GU_N, HH);
    // 14) down projection + residual: out = h + ffn @ wdown
    hgemm<1><<<dim3(TT/BM, HH/BN), 256, SMEM_BYTES>>>(p_ffn, p_wd, p_h, out, TT, HH, II);
}

// round 15
// speedup vs baseline: 1.2163x; 1.0247x over previous
#include <cuda_runtime.h>
#include <cuda_fp16.h>
#include <cstdint>
#include <math.h>

// ---------------- problem constants ----------------
#define BB 2
#define SS 1024
#define HH 4096
#define NQ 32
#define NKV 8
#define DD 128
#define II 11008
#define TT (BB*SS)          // 2048 tokens
#define EPS 1e-5f

#define QKV_N (HH + 2*NKV*DD)   // 6144
#define GU_N  (2*II)            // 22016 (8-col-block interleaved gate/up)

// ---------------- scratch (device globals, no allocation) ----------------
__device__ __half g_hin  [(size_t)TT*HH];
__device__ __half g_qkv  [(size_t)TT*QKV_N];
__device__ __half g_qh   [(size_t)TT*NQ*DD];
__device__ __half g_kh   [(size_t)TT*NKV*DD];
__device__ __half g_vt   [(size_t)TT*NKV*DD];
__device__ __half g_attn [(size_t)TT*HH];
__device__ float  g_h    [(size_t)TT*HH];
__device__ __half g_ffn  [(size_t)TT*II];
__device__ __half g_wqkv [(size_t)HH*QKV_N];   // [K=4096][6144] half (no transpose)
__device__ __half g_wo_h [(size_t)HH*HH];      // [K][N]
__device__ __half g_wgu  [(size_t)HH*GU_N];    // [K][2I], 8-col blocks interleaved
__device__ __half g_wd_h [(size_t)II*HH];      // [K=11008][4096]

// ================= helpers =================
__device__ __forceinline__ uint32_t smem_u32(const void* p) {
    uint32_t a;
    asm("{ .reg .u64 t; cvta.to.shared.u64 t, %1; cvt.u32.u64 %0, t; }" : "=r"(a) : "l"(p));
    return a;
}
__device__ __forceinline__ void cp_async16(uint32_t dst, const void* src) {
    asm volatile("cp.async.cg.shared.global [%0], [%1], 16;" :: "r"(dst), "l"(src));
}
#define CP_COMMIT() asm volatile("cp.async.commit_group;" ::: "memory")
#define CP_WAIT(n)  asm volatile("cp.async.wait_group %0;" :: "n"(n) : "memory")

__device__ __forceinline__ void ldsm4(uint32_t addr, uint32_t& r0, uint32_t& r1,
                                      uint32_t& r2, uint32_t& r3) {
    asm volatile("ldmatrix.sync.aligned.m8n8.x4.shared.b16 {%0,%1,%2,%3}, [%4];"
                 : "=r"(r0), "=r"(r1), "=r"(r2), "=r"(r3) : "r"(addr));
}
__device__ __forceinline__ void ldsm4t(uint32_t addr, uint32_t& r0, uint32_t& r1,
                                       uint32_t& r2, uint32_t& r3) {
    asm volatile("ldmatrix.sync.aligned.m8n8.x4.trans.shared.b16 {%0,%1,%2,%3}, [%4];"
                 : "=r"(r0), "=r"(r1), "=r"(r2), "=r"(r3) : "r"(addr));
}
__device__ __forceinline__ void mma_f16(float* d, const uint32_t* a, const uint32_t* b) {
    asm volatile(
        "mma.sync.aligned.m16n8k16.row.col.f32.f16.f16.f32 "
        "{%0,%1,%2,%3}, {%4,%5,%6,%7}, {%8,%9}, {%0,%1,%2,%3};\n"
        : "+f"(d[0]), "+f"(d[1]), "+f"(d[2]), "+f"(d[3])
        : "r"(a[0]), "r"(a[1]), "r"(a[2]), "r"(a[3]), "r"(b[0]), "r"(b[1]));
}
__device__ __forceinline__ uint32_t h2pack(float a, float b) {
    __half2 h = __floats2half2_rn(a, b);
    return *(uint32_t*)&h;
}

// ================= fp16 tensor-core GEMM (NT, R14-validated) =================
#define BM 128
#define BN 128
#define BK 64
#define STAGES 3
#define AROWB 144
#define BROWB 272
#define A_TILEB (128*AROWB)
#define B_TILEB (64*BROWB)
#define STAGE_B (A_TILEB + B_TILEB)
#define SMEM_BYTES (STAGES*STAGE_B)

__device__ __forceinline__ void load_stage(uint32_t sb, int st,
                                           const __half* __restrict__ A,
                                           const __half* __restrict__ B,
                                           int m0, int n0, int k0, int K, int N) {
    int t = threadIdx.x;
    uint32_t sA = sb + st * STAGE_B;
    uint32_t sB = sA + A_TILEB;
    #pragma unroll
    for (int i = 0; i < 4; i++) {
        int c = t + i * 256;
        int row = c >> 3, ch = c & 7;
        cp_async16(sA + (uint32_t)(row * AROWB + ch * 16),
                   A + (size_t)(m0 + row) * K + k0 + ch * 8);
    }
    #pragma unroll
    for (int i = 0; i < 4; i++) {
        int c = t + i * 256;
        int row = c >> 4, ch = c & 15;
        cp_async16(sB + (uint32_t)(row * BROWB + ch * 16),
                   B + (size_t)(k0 + row) * N + n0 + ch * 8);
    }
}

template<int EPI>
__global__ void __launch_bounds__(256, 2)
hgemm(const __half* __restrict__ A, const __half* __restrict__ B,
      const float* __restrict__ res, void* __restrict__ Cout,
      int M, int N, int K) {
    extern __shared__ char smem[];
    uint32_t sb = smem_u32(smem);
    int tid = threadIdx.x, wid = tid >> 5, lane = tid & 31;
    int wm = wid >> 2, wn = wid & 3;
    int group = lane >> 2, tig = lane & 3;
    int m0 = blockIdx.x * BM, n0 = blockIdx.y * BN;

    int rowoff  = (lane & 7) + ((lane >> 3) & 1) * 8;
    int koff    = (lane >> 4) * 16;
    int browoff = (lane & 7) + ((lane >> 3) & 1) * 8;
    int bnoff   = (lane >> 4) * 8;

    float acc[4][4][4];
    #pragma unroll
    for (int mt = 0; mt < 4; mt++)
        #pragma unroll
        for (int nt = 0; nt < 4; nt++)
            #pragma unroll
            for (int j = 0; j < 4; j++) acc[mt][nt][j] = 0.f;

    int nk = K / BK;
    #pragma unroll
    for (int s = 0; s < STAGES - 1; s++) {
        load_stage(sb, s, A, B, m0, n0, s * BK, K, N);
        CP_COMMIT();
    }

    int st = 0;
    for (int kt = 0; kt < nk; kt++) {
        CP_WAIT(STAGES - 2);
        __syncthreads();

        int nxt = kt + STAGES - 1;
        if (nxt < nk) {
            int nst = st + (STAGES - 1); if (nst >= STAGES) nst -= STAGES;
            load_stage(sb, nst, A, B, m0, n0, nxt * BK, K, N);
        }
        CP_COMMIT();

        uint32_t sA = sb + st * STAGE_B;
        uint32_t sB = sA + A_TILEB;

        #pragma unroll
        for (int ks = 0; ks < 4; ks++) {
            uint32_t a[4][4], bfr[4][2];
            #pragma unroll
            for (int mt = 0; mt < 4; mt++) {
                uint32_t ad = sA + (uint32_t)((wm * 64 + mt * 16 + rowoff) * AROWB + ks * 32 + koff);
                ldsm4(ad, a[mt][0], a[mt][1], a[mt][2], a[mt][3]);
            }
            #pragma unroll
            for (int np = 0; np < 2; np++) {
                uint32_t bd = sB + (uint32_t)((ks * 16 + browoff) * BROWB
                                              + (wn * 32 + np * 16 + bnoff) * 2);
                uint32_t r0, r1, r2, r3;
                ldsm4t(bd, r0, r1, r2, r3);
                bfr[2*np][0]   = r0; bfr[2*np][1]   = r1;
                bfr[2*np+1][0] = r2; bfr[2*np+1][1] = r3;
            }
            #pragma unroll
            for (int mt = 0; mt < 4; mt++)
                #pragma unroll
                for (int nt = 0; nt < 4; nt++)
                    mma_f16(acc[mt][nt], a[mt], bfr[nt]);
        }
        if (++st == STAGES) st = 0;
    }

    // epilogue
    if (EPI == 2) {
        __half* Ch = (__half*)Cout;
        int No = N >> 1;
        #pragma unroll
        for (int mt = 0; mt < 4; mt++) {
            int r0 = m0 + wm * 64 + mt * 16 + group;
            #pragma unroll
            for (int a = 0; a < 2; a++) {
                int base = n0 + wn * 32 + 16 * a;
                int j = (base >> 1) + 2 * tig;
                float g0 = acc[mt][2*a][0],  g0b = acc[mt][2*a][1];
                float u0 = acc[mt][2*a+1][0], u0b = acc[mt][2*a+1][1];
                float g1 = acc[mt][2*a][2],  g1b = acc[mt][2*a][3];
                float u1 = acc[mt][2*a+1][2], u1b = acc[mt][2*a+1][3];
                __half2 w0 = __floats2half2_rn(g0 / (1.f + __expf(-g0)) * u0,
                                               g0b / (1.f + __expf(-g0b)) * u0b);
                __half2 w1 = __floats2half2_rn(g1 / (1.f + __expf(-g1)) * u1,
                                               g1b / (1.f + __expf(-g1b)) * u1b);
                *(__half2*)(Ch + (size_t)r0 * No + j)       = w0;
                *(__half2*)(Ch + (size_t)(r0 + 8) * No + j) = w1;
            }
        }
    } else {
        #pragma unroll
        for (int mt = 0; mt < 4; mt++) {
            int r0 = m0 + wm * 64 + mt * 16 + group;
            #pragma unroll
            for (int nt = 0; nt < 4; nt++) {
                int c = n0 + wn * 32 + nt * 8 + 2 * tig;
                if (EPI == 3) {
                    __half* Ch = (__half*)Cout;
                    size_t i0 = (size_t)r0 * N + c;
                    size_t i1 = (size_t)(r0 + 8) * N + c;
                    *(__half2*)(Ch + i0) = __floats2half2_rn(acc[mt][nt][0], acc[mt][nt][1]);
                    *(__half2*)(Ch + i1) = __floats2half2_rn(acc[mt][nt][2], acc[mt][nt][3]);
                } else {
                    float* C = (float*)Cout;
                    size_t i0 = (size_t)r0 * N + c;
                    size_t i1 = (size_t)(r0 + 8) * N + c;
                    float2 v0 = make_float2(acc[mt][nt][0], acc[mt][nt][1]);
                    float2 v1 = make_float2(acc[mt][nt][2], acc[mt][nt][3]);
                    if (EPI == 1) {
                        float2 r0v = *(const float2*)(res + i0);
                        float2 r1v = *(const float2*)(res + i1);
                        v0.x += r0v.x; v0.y += r0v.y;
                        v1.x += r1v.x; v1.y += r1v.y;
                    }
                    *(float2*)(C + i0) = v0;
                    *(float2*)(C + i1) = v1;
                }
            }
        }
    }
}

// ================= streaming converts (no transpose) =================
// W[K][N] fp32 -> Wh[K][dstN] half at column offset; 16 floats per thread.
__global__ void conv_h(const float* __restrict__ W, __half* __restrict__ Wh,
                       int N, int dstN, long colOff, long total16) {
    long i = (long)blockIdx.x * 256 + threadIdx.x;
    if (i >= total16) return;
    int n16 = N >> 4;
    long row = i / n16;
    int c = (int)(i - row * n16) * 16;
    const float4* src = (const float4*)(W + row * (size_t)N + c);
    float4 v0 = src[0], v1 = src[1], v2 = src[2], v3 = src[3];
    uint4 o0, o1;
    o0.x = h2pack(v0.x, v0.y); o0.y = h2pack(v0.z, v0.w);
    o0.z = h2pack(v1.x, v1.y); o0.w = h2pack(v1.z, v1.w);
    o1.x = h2pack(v2.x, v2.y); o1.y = h2pack(v2.z, v2.w);
    o1.z = h2pack(v3.x, v3.y); o1.w = h2pack(v3.z, v3.w);
    __half* d = Wh + row * (size_t)dstN + colOff + c;
    *(uint4*)d       = o0;
    *(uint4*)(d + 8) = o1;
}

// gate[K][I], up[K][I] -> wgu[K][2I], 8-col blocks interleaved.
__global__ void conv_gu(const float* __restrict__ G, const float* __restrict__ U,
                        __half* __restrict__ Wt, long total) {
    long i = (long)blockIdx.x * 256 + threadIdx.x;
    if (i >= total) return;                 // total = K * (I/8)
    int nb = II >> 3;
    long k = i / nb;
    int a = (int)(i - k * nb);
    const float* gp = G + k * (size_t)II + a * 8;
    const float* up = U + k * (size_t)II + a * 8;
    float4 g0 = *(const float4*)gp,      g1 = *(const float4*)(gp + 4);
    float4 u0 = *(const float4*)up,      u1 = *(const float4*)(up + 4);
    uint4 w0, w1;
    w0.x = h2pack(g0.x, g0.y); w0.y = h2pack(g0.z, g0.w);
    w0.z = h2pack(g1.x, g1.y); w0.w = h2pack(g1.z, g1.w);
    w1.x = h2pack(u0.x, u0.y); w1.y = h2pack(u0.z, u0.w);
    w1.z = h2pack(u1.x, u1.y); w1.w = h2pack(u1.z, u1.w);
    __half* d = Wt + k * (size_t)GU_N + a * 16;
    *(uint4*)d       = w0;
    *(uint4*)(d + 8) = w1;
}

// ================= rmsnorm (half output) =================
__global__ void rmsnorm_kernel(const float* __restrict__ x,
                               const float* __restrict__ w,
                               __half* __restrict__ out) {
    int row = blockIdx.x;
    const float* xr = x + (size_t)row * HH;
    float ss = 0.f;
    for (int i = threadIdx.x; i < HH; i += blockDim.x) {
        float v = xr[i];
        ss = fmaf(v, v, ss);
    }
    __shared__ float red[32];
    int lane = threadIdx.x & 31, warp = threadIdx.x >> 5;
    #pragma unroll
    for (int off = 16; off; off >>= 1) ss += __shfl_xor_sync(~0u, ss, off);
    if (lane == 0) red[warp] = ss;
    __syncthreads();
    int nwarp = blockDim.x >> 5;
    if (warp == 0) {
        float v = (lane < nwarp) ? red[lane] : 0.f;
        #pragma unroll
        for (int off = 16; off; off >>= 1) v += __shfl_xor_sync(~0u, v, off);
        if (lane == 0) red[0] = v;
    }
    __syncthreads();
    float inv = rsqrtf(red[0] / (float)HH + EPS);
    __half* orow = out + (size_t)row * HH;
    for (int i = threadIdx.x; i < HH; i += blockDim.x)
        orow[i] = __float2half_rn(xr[i] * inv * w[i]);
}

// ================= fused RoPE extract: q (scaled) + k =================
__global__ void rope_qk(const __half* __restrict__ qkv,
                        const float* __restrict__ cosT,
                        const float* __restrict__ sinT,
                        __half* __restrict__ qh,
                        __half* __restrict__ kh) {
    int idx = blockIdx.x * blockDim.x + threadIdx.x;
    if (idx >= TT * (NQ + NKV) * 64) return;
    const float qscale = 0.08838834764831845f;
    int d  = idx & 63;
    int hh = (idx >> 6) % (NQ + NKV);
    int t  = idx / (64 * (NQ + NKV));
    int s  = t % SS, b = t / SS;
    float c1 = cosT[s*DD + d],      s1 = sinT[s*DD + d];
    float c2 = cosT[s*DD + d + 64], s2 = sinT[s*DD + d + 64];
    if (hh < NQ) {
        const __half* p = qkv + (size_t)t * QKV_N + hh * DD;
        float x1 = __half2float(p[d]), x2 = __half2float(p[d + 64]);
        size_t row = ((size_t)(b*NQ + hh)*SS + s) * DD;
        qh[row + d]      = __float2half_rn((x1 * c1 - x2 * s1) * qscale);
        qh[row + d + 64] = __float2half_rn((x2 * c2 + x1 * s2) * qscale);
    } else {
        int h = hh - NQ;
        const __half* p = qkv + (size_t)t * QKV_N + HH + h * DD;
        float x1 = __half2float(p[d]), x2 = __half2float(p[d + 64]);
        size_t row = ((size_t)(b*NKV + h)*SS + s) * DD;
        kh[row + d]      = __float2half_rn(x1 * c1 - x2 * s1);
        kh[row + d + 64] = __float2half_rn(x2 * c2 + x1 * s2);
    }
}

// ================= V extract + transpose: vt[b,kvh,d,s] =================
__global__ void v_trans(const __half* __restrict__ qkv, __half* __restrict__ vt) {
    __shared__ __half tile[32][33];
    int s0 = blockIdx.x * 32, d0 = blockIdx.y * 32;
    int bk = blockIdx.z;
    int b = bk / NKV, kvh = bk % NKV;
    int tx = threadIdx.x, ty = threadIdx.y;
    #pragma unroll
    for (int i = 0; i < 32; i += 8) {
        int s = s0 + ty + i;
        tile[ty + i][tx] = qkv[(size_t)(b*SS + s) * QKV_N + HH + NKV*DD + kvh*DD + d0 + tx];
    }
    __syncthreads();
    #pragma unroll
    for (int i = 0; i < 32; i += 8)
        vt[((size_t)(b*NKV + kvh)*DD + d0 + ty + i) * SS + s0 + tx] = tile[tx][ty + i];
}

// ================= fp16 flash attention (unchanged) =================
#define AQT 64
#define AKT 64
#define QSTR 136
#define VSTR 72
#define AQ_BYTES (AQT*QSTR*2)
#define AK_BYTES (AKT*QSTR*2)
#define AV_BYTES (DD*VSTR*2)
#define ATT_SMEM (AQ_BYTES + 2*AK_BYTES + 2*AV_BYTES)

__global__ void __launch_bounds__(128, 2)
fattn(const __half* __restrict__ qh, const __half* __restrict__ kh,
      const __half* __restrict__ vt, __half* __restrict__ o) {
    extern __shared__ char sm[];
    uint32_t sb = smem_u32(sm);
    uint32_t sQ = sb;
    uint32_t sK = sQ + AQ_BYTES;
    uint32_t sV = sK + 2*AK_BYTES;

    int b = blockIdx.z, h = blockIdx.y;
    int qt = gridDim.x - 1 - blockIdx.x;
    int kvh = h >> 2;
    int q0 = qt * AQT;
    int tid = threadIdx.x, w = tid >> 5, lane = tid & 31;
    int g = lane >> 2, tig = lane & 3;
    int rowoff = lane & 15;
    int kofs   = (lane >> 4) * 16;

    const __half* qbase = qh + ((size_t)(b*NQ + h)*SS + q0) * DD;
    const __half* kbase = kh + ((size_t)(b*NKV + kvh)*SS) * DD;
    const __half* vbase = vt + ((size_t)(b*NKV + kvh)*DD) * SS;

    for (int i = tid; i < 1024; i += 128) {
        int r = i >> 4, c = i & 15;
        cp_async16(sQ + (uint32_t)(r*(QSTR*2) + c*16), qbase + (size_t)r*DD + c*8);
    }
    CP_COMMIT();

    int nt = qt + 1;
    {
        uint32_t dK = sK, dV = sV;
        for (int i = tid; i < 1024; i += 128) {
            int r = i >> 4, c = i & 15;
            cp_async16(dK + (uint32_t)(r*(QSTR*2) + c*16), kbase + (size_t)r*DD + c*8);
        }
        for (int i = tid; i < 1024; i += 128) {
            int r = i >> 3, c = i & 7;
            cp_async16(dV + (uint32_t)(r*(VSTR*2) + c*16), vbase + (size_t)r*SS + c*8);
        }
    }
    CP_COMMIT();

    CP_WAIT(1);
    __syncthreads();
    uint32_t qfr[8][4];
    #pragma unroll
    for (int kb = 0; kb < 8; kb++)
        ldsm4(sQ + (uint32_t)((w*16 + rowoff)*(QSTR*2) + kb*32 + kofs),
              qfr[kb][0], qfr[kb][1], qfr[kb][2], qfr[kb][3]);

    float m0v = -INFINITY, m1v = -INFINITY, l0 = 0.f, l1 = 0.f;
    float oac[16][4];
    #pragma unroll
    for (int i = 0; i < 16; i++)
        #pragma unroll
        for (int j = 0; j < 4; j++) oac[i][j] = 0.f;

    for (int t = 0; t < nt; t++) {
        if (t + 1 < nt) {
            uint32_t dK = sK + ((t+1)&1) * AK_BYTES;
            uint32_t dV = sV + ((t+1)&1) * AV_BYTES;
            const __half* kp = kbase + (size_t)(t+1)*AKT*DD;
            const __half* vp = vbase + (t+1)*AKT;
            for (int i = tid; i < 1024; i += 128) {
                int r = i >> 4, c = i & 15;
                cp_async16(dK + (uint32_t)(r*(QSTR*2) + c*16), kp + (size_t)r*DD + c*8);
            }
            for (int i = tid; i < 1024; i += 128) {
                int r = i >> 3, c = i & 7;
                cp_async16(dV + (uint32_t)(r*(VSTR*2) + c*16), vp + (size_t)r*SS + c*8);
            }
        }
        CP_COMMIT();
        CP_WAIT(1);
        __syncthreads();

        uint32_t cK = sK + (t&1) * AK_BYTES;
        uint32_t cV = sV + (t&1) * AV_BYTES;

        float s[8][4];
        #pragma unroll
        for (int j = 0; j < 8; j++)
            #pragma unroll
            for (int c = 0; c < 4; c++) s[j][c] = 0.f;

        #pragma unroll
        for (int kb = 0; kb < 8; kb++) {
            #pragma unroll
            for (int np = 0; np < 4; np++) {
                uint32_t r0, r1, r2, r3;
                ldsm4(cK + (uint32_t)((16*np + rowoff)*(QSTR*2) + kb*32 + kofs),
                      r0, r1, r2, r3);
                uint32_t b0[2] = {r0, r2}, b1[2] = {r1, r3};
                mma_f16(s[2*np],   qfr[kb], b0);
                mma_f16(s[2*np+1], qfr[kb], b1);
            }
        }

        if (t == qt) {
            int r0l = w*16 + g, r1l = r0l + 8;
            #pragma unroll
            for (int j = 0; j < 8; j++) {
                int c0 = 8*j + 2*tig;
                if (c0     > r0l) s[j][0] = -1e30f;
                if (c0 + 1 > r0l) s[j][1] = -1e30f;
                if (c0     > r1l) s[j][2] = -1e30f;
                if (c0 + 1 > r1l) s[j][3] = -1e30f;
            }
        }

        float tm0 = -1e30f, tm1 = -1e30f;
        #pragma unroll
        for (int j = 0; j < 8; j++) {
            tm0 = fmaxf(tm0, fmaxf(s[j][0], s[j][1]));
            tm1 = fmaxf(tm1, fmaxf(s[j][2], s[j][3]));
        }
        tm0 = fmaxf(tm0, __shfl_xor_sync(~0u, tm0, 1));
        tm0 = fmaxf(tm0, __shfl_xor_sync(~0u, tm0, 2));
        tm1 = fmaxf(tm1, __shfl_xor_sync(~0u, tm1, 1));
        tm1 = fmaxf(tm1, __shfl_xor_sync(~0u, tm1, 2));

        float mn0 = fmaxf(m0v, tm0), mn1 = fmaxf(m1v, tm1);
        float a0 = __expf(m0v - mn0), a1 = __expf(m1v - mn1);
        m0v = mn0; m1v = mn1;

        float ts0 = 0.f, ts1 = 0.f;
        #pragma unroll
        for (int j = 0; j < 8; j++) {
            s[j][0] = __expf(s[j][0] - mn0);
            s[j][1] = __expf(s[j][1] - mn0);
            s[j][2] = __expf(s[j][2] - mn1);
            s[j][3] = __expf(s[j][3] - mn1);
            ts0 += s[j][0] + s[j][1];
            ts1 += s[j][2] + s[j][3];
        }
        ts0 += __shfl_xor_sync(~0u, ts0, 1);
        ts0 += __shfl_xor_sync(~0u, ts0, 2);
        ts1 += __shfl_xor_sync(~0u, ts1, 1);
        ts1 += __shfl_xor_sync(~0u, ts1, 2);
        l0 = l0 * a0 + ts0;
        l1 = l1 * a1 + ts1;

        #pragma unroll
        for (int i = 0; i < 16; i++) {
            oac[i][0] *= a0; oac[i][1] *= a0;
            oac[i][2] *= a1; oac[i][3] *= a1;
        }

        uint32_t pf[4][4];
        #pragma unroll
        for (int jj = 0; jj < 4; jj++) {
            pf[jj][0] = h2pack(s[2*jj][0],   s[2*jj][1]);
            pf[jj][1] = h2pack(s[2*jj][2],   s[2*jj][3]);
            pf[jj][2] = h2pack(s[2*jj+1][0], s[2*jj+1][1]);
            pf[jj][3] = h2pack(s[2*jj+1][2], s[2*jj+1][3]);
        }

        #pragma unroll
        for (int jj = 0; jj < 4; jj++) {
            #pragma unroll
            for (int dp = 0; dp < 8; dp++) {
                uint32_t r0, r1, r2, r3;
                ldsm4(cV + (uint32_t)((16*dp + rowoff)*(VSTR*2) + jj*32 + kofs),
                      r0, r1, r2, r3);
                uint32_t b0[2] = {r0, r2}, b1[2] = {r1, r3};
                mma_f16(oac[2*dp],   pf[jj], b0);
                mma_f16(oac[2*dp+1], pf[jj], b1);
            }
        }
        __syncthreads();
    }

    float il0 = 1.f / l0, il1 = 1.f / l1;
    int r0g = q0 + w*16 + g;
    __half* ob0 = o + (size_t)(b*SS + r0g) * HH + h * DD;
    __half* ob1 = ob0 + (size_t)8 * HH;
    #pragma unroll
    for (int ntl = 0; ntl < 16; ntl++) {
        int d = 8*ntl + 2*tig;
        __half2 v0 = __floats2half2_rn(oac[ntl][0]*il0, oac[ntl][1]*il0);
        __half2 v1 = __floats2half2_rn(oac[ntl][2]*il1, oac[ntl][3]*il1);
        *(__half2*)(ob0 + d) = v0;
        *(__half2*)(ob1 + d) = v1;
    }
}

// ================= launch =================
extern "C" void kernel_launch(void* const* d_in, const int* in_sizes, int n_in,
                              void* d_out, int out_size) {
    const float* x     = (const float*)d_in[0];
    const float* cosT  = (const float*)d_in[1];
    const float* sinT  = (const float*)d_in[2];
    const float* anw   = (const float*)d_in[3];
    const float* fnw   = (const float*)d_in[4];
    const float* wq    = (const float*)d_in[5];
    const float* wk    = (const float*)d_in[6];
    const float* wv    = (const float*)d_in[7];
    const float* wo    = (const float*)d_in[8];
    const float* wgate = (const float*)d_in[9];
    const float* wup   = (const float*)d_in[10];
    const float* wdown = (const float*)d_in[11];
    float* out = (float*)d_out;

    __half *p_hin, *p_qkv, *p_qh, *p_kh, *p_vt, *p_attn, *p_ffn, *p_wqkv, *p_wo, *p_wgu, *p_wd;
    float *p_h;
    cudaGetSymbolAddress((void**)&p_hin,  g_hin);
    cudaGetSymbolAddress((void**)&p_qkv,  g_qkv);
    cudaGetSymbolAddress((void**)&p_qh,   g_qh);
    cudaGetSymbolAddress((void**)&p_kh,   g_kh);
    cudaGetSymbolAddress((void**)&p_vt,   g_vt);
    cudaGetSymbolAddress((void**)&p_attn, g_attn);
    cudaGetSymbolAddress((void**)&p_h,    g_h);
    cudaGetSymbolAddress((void**)&p_ffn,  g_ffn);
    cudaGetSymbolAddress((void**)&p_wqkv, g_wqkv);
    cudaGetSymbolAddress((void**)&p_wo,   g_wo_h);
    cudaGetSymbolAddress((void**)&p_wgu,  g_wgu);
    cudaGetSymbolAddress((void**)&p_wd,   g_wd_h);

    cudaFuncSetAttribute(hgemm<0>, cudaFuncAttributeMaxDynamicSharedMemorySize, SMEM_BYTES);
    cudaFuncSetAttribute(hgemm<1>, cudaFuncAttributeMaxDynamicSharedMemorySize, SMEM_BYTES);
    cudaFuncSetAttribute(hgemm<2>, cudaFuncAttributeMaxDynamicSharedMemorySize, SMEM_BYTES);
    cudaFuncSetAttribute(hgemm<3>, cudaFuncAttributeMaxDynamicSharedMemorySize, SMEM_BYTES);
    cudaFuncSetAttribute(fattn,    cudaFuncAttributeMaxDynamicSharedMemorySize, ATT_SMEM);

    // side stream for weight converts (fork-join, graph-capturable)
    cudaStream_t s2;
    cudaStreamCreateWithFlags(&s2, cudaStreamNonBlocking);
    cudaEvent_t eStart, eQKV, eWO, eGU, eWD;
    cudaEventCreateWithFlags(&eStart, cudaEventDisableTiming);
    cudaEventCreateWithFlags(&eQKV,  cudaEventDisableTiming);
    cudaEventCreateWithFlags(&eWO,   cudaEventDisableTiming);
    cudaEventCreateWithFlags(&eGU,   cudaEventDisableTiming);
    cudaEventCreateWithFlags(&eWD,   cudaEventDisableTiming);

    cudaEventRecord(eStart, 0);
    cudaStreamWaitEvent(s2, eStart, 0);

    // s2: weight converts
    {
        long t16;
        t16 = (long)HH*HH/16;
        conv_h<<<(unsigned)((t16+255)/256), 256, 0, s2>>>(wq, p_wqkv, HH, QKV_N, 0, t16);
        t16 = (long)HH*(NKV*DD)/16;
        conv_h<<<(unsigned)((t16+255)/256), 256, 0, s2>>>(wk, p_wqkv, NKV*DD, QKV_N, HH, t16);
        conv_h<<<(unsigned)((t16+255)/256), 256, 0, s2>>>(wv, p_wqkv, NKV*DD, QKV_N, HH+NKV*DD, t16);
        cudaEventRecord(eQKV, s2);
        t16 = (long)HH*HH/16;
        conv_h<<<(unsigned)((t16+255)/256), 256, 0, s2>>>(wo, p_wo, HH, HH, 0, t16);
        cudaEventRecord(eWO, s2);
        long tg = (long)HH * (II/8);
        conv_gu<<<(unsigned)((tg+255)/256), 256, 0, s2>>>(wgate, wup, p_wgu, tg);
        cudaEventRecord(eGU, s2);
        t16 = (long)II*HH/16;
        conv_h<<<(unsigned)((t16+255)/256), 256, 0, s2>>>(wdown, p_wd, HH, HH, 0, t16);
        cudaEventRecord(eWD, s2);
    }

    // main stream
    rmsnorm_kernel<<<TT, 256>>>(x, anw, p_hin);
    cudaStreamWaitEvent(0, eQKV, 0);
    hgemm<3><<<dim3(TT/BM, QKV_N/BN), 256, SMEM_BYTES>>>(p_hin, p_wqkv, nullptr, p_qkv, TT, QKV_N, HH);
    {
        int tqk = TT * (NQ + NKV) * 64;
        rope_qk<<<(tqk + 255) / 256, 256>>>(p_qkv, cosT, sinT, p_qh, p_kh);
        dim3 tb(32, 8);
        v_trans<<<dim3(SS/32, DD/32, BB*NKV), tb>>>(p_qkv, p_vt);
    }
    fattn<<<dim3(SS/AQT, NQ, BB), 128, ATT_SMEM>>>(p_qh, p_kh, p_vt, p_attn);
    cudaStreamWaitEvent(0, eWO, 0);
    hgemm<1><<<dim3(TT/BM, HH/BN), 256, SMEM_BYTES>>>(p_attn, p_wo, x, p_h, TT, HH, HH);
    rmsnorm_kernel<<<TT, 256>>>(p_h, fnw, p_hin);
    cudaStreamWaitEvent(0, eGU, 0);
    hgemm<2><<<dim3(TT/BM, GU_N/BN), 256, SMEM_BYTES>>>(p_hin, p_wgu, nullptr, p_ffn, TT, GU_N, HH);
    cudaStreamWaitEvent(0, eWD, 0);
    hgemm<1><<<dim3(TT/BM, HH/BN), 256, SMEM_BYTES>>>(p_ffn, p_wd, p_h, out, TT, HH, II);
}